// round 8
// baseline (speedup 1.0000x reference)
#include <cuda_runtime.h>

#define NSAMP 32
#define OUTP  64
#define MID   8
#define MAXSETS 50000

// ---------------- device scratch (zero-initialized at module load) ----------------
__device__ double g_stats[4];              // k_prep re-zeroes after reading
__device__ float  g_c0[3];                 // t0 = tr.x*c0[0] + tr.y*c0[1] + c0[2]
__device__ float  g_c1[3];
__device__ float  g_A[MID][2];             // folded relu(t) -> q coupling
__device__ float  g_bq[MID];               // b_q + Wq . b_p2
__device__ float4 g_buf4[MAXSETS * 4];     // per set: [gsum(8) | res(8)]; k_final re-zeroes

// ---------------- packed f32x2 helpers ----------------
__device__ __forceinline__ unsigned long long pk2(float a, float b) {
    unsigned long long r;
    asm("mov.b64 %0, {%1,%2};" : "=l"(r) : "f"(a), "f"(b));
    return r;
}
__device__ __forceinline__ void fma2(unsigned long long &d, unsigned long long a, unsigned long long b) {
    asm("fma.rn.f32x2 %0, %1, %2, %0;" : "+l"(d) : "l"(a), "l"(b));
}
__device__ __forceinline__ float2 upk2(unsigned long long a) {
    float2 r;
    asm("mov.b64 {%0,%1}, %2;" : "=f"(r.x), "=f"(r.y) : "l"(a));
    return r;
}
__device__ __forceinline__ void red4(float4* p, float a, float b, float c, float d) {
    asm volatile("red.global.add.v4.f32 [%0], {%1,%2,%3,%4};"
                 :: "l"(p), "f"(a), "f"(b), "f"(c), "f"(d) : "memory");
}

// ---------------- K1: BatchNorm batch statistics over t = tr @ Wp1^T ----------------
__global__ void k_stats(const float2* __restrict__ tr, const float* __restrict__ Wp1, int N) {
    float w00 = __ldg(Wp1 + 0), w01 = __ldg(Wp1 + 1);
    float w10 = __ldg(Wp1 + 2), w11 = __ldg(Wp1 + 3);
    float s0 = 0.f, s1 = 0.f, q0 = 0.f, q1 = 0.f;
    for (int n = blockIdx.x * blockDim.x + threadIdx.x; n < N; n += gridDim.x * blockDim.x) {
        float2 t = __ldg(&tr[n]);
        float t0 = t.x * w00 + t.y * w01;
        float t1 = t.x * w10 + t.y * w11;
        s0 += t0; s1 += t1; q0 += t0 * t0; q1 += t1 * t1;
    }
    #pragma unroll
    for (int o = 16; o; o >>= 1) {
        s0 += __shfl_xor_sync(0xffffffffu, s0, o);
        s1 += __shfl_xor_sync(0xffffffffu, s1, o);
        q0 += __shfl_xor_sync(0xffffffffu, q0, o);
        q1 += __shfl_xor_sync(0xffffffffu, q1, o);
    }
    if ((threadIdx.x & 31) == 0) {
        atomicAdd(&g_stats[0], (double)s0);
        atomicAdd(&g_stats[1], (double)s1);
        atomicAdd(&g_stats[2], (double)q0);
        atomicAdd(&g_stats[3], (double)q1);
    }
}

// ---------------- K2: fold BN + p-branch into small constants (re-zero g_stats) -------
__global__ void k_prep(const float* __restrict__ Wq, const float* __restrict__ bq,
                       const float* __restrict__ Wp1, const float* __restrict__ gamma,
                       const float* __restrict__ beta, const float* __restrict__ Wp2,
                       const float* __restrict__ bp2, int N) {
    int t = threadIdx.x;
    if (t < 2) {
        double mean = g_stats[t] / (double)N;
        double var  = g_stats[2 + t] / (double)N - mean * mean;
        float sc = gamma[t] / sqrtf((float)var + 1e-5f);
        float* c = t ? g_c1 : g_c0;
        c[0] = Wp1[t * 2 + 0] * sc;
        c[1] = Wp1[t * 2 + 1] * sc;
        c[2] = beta[t] - (float)mean * sc;
    }
    if (t < MID) {
        float a0 = 0.f, a1 = 0.f, bb = bq[t];
        for (int k = 0; k < OUTP; k++) {
            float w = Wq[t * OUTP + k];
            a0 += w * Wp2[k * 2 + 0];
            a1 += w * Wp2[k * 2 + 1];
            bb += w * bp2[k];
        }
        g_A[t][0] = a0; g_A[t][1] = a1; g_bq[t] = bb;
    }
    __syncwarp();
    if (t < 4) g_stats[t] = 0.0;   // restore zero-invariant for next replay
}

// ---------------- K3: fused main pass ----------------
// Block = 128 threads (4 warps), each warp owns ONE set (8KB tile) -> 6 blocks/SM,
// 24 warps/SM (2x occupancy of R7). Thread = one sample row in the mainloop.
__global__ void __launch_bounds__(128, 6) k_main(
    const float4* __restrict__ x, const float2* __restrict__ tr,
    const int* __restrict__ idx, const float* __restrict__ Wq,
    const float* __restrict__ Wv, const float* __restrict__ bv,
    float* __restrict__ out, int nsets)
{
    __shared__ float2 sW[MID * OUTP];            // 4KB interleaved (Wq,Wv)
    __shared__ float  sX[4][NSAMP * OUTP];       // 32KB: [warp][sample*64 swizzled]

    int tid = threadIdx.x;
    #pragma unroll
    for (int i = tid; i < MID * OUTP; i += 128)
        sW[i] = make_float2(__ldg(&Wq[i]), __ldg(&Wv[i]));
    __syncthreads();

    int warp = tid >> 5, lane = tid & 31;
    int sset = blockIdx.x * 4 + warp;
    if (sset >= nsets) return;                   // uniform per warp; no later __syncthreads

    // ---------------- staging + features (coalesced) ----------------
    int half = lane >> 4;          // sample parity this lane loads
    int j    = lane & 15;          // float4 group (channels 4j..4j+3)
    {
        const float4* src = x + (size_t)sset * NSAMP * 16;
        float* dst = sX[warp];
        float f0 = 0.f, f1 = 0.f, f2 = 0.f, f3 = 0.f;
        #pragma unroll
        for (int it = 0; it < 16; it++) {
            int s = it * 2 + half;
            float4 v = __ldg(&src[s * 16 + j]);  // warp: 512B contiguous
            f0 += v.x; f1 += v.y; f2 += v.z; f3 += v.w;
            int jp = j ^ (s & 7);                // XOR swizzle
            *(float4*)&dst[s * 64 + jp * 4] = v;
        }
        f0 += __shfl_xor_sync(0xffffffffu, f0, 16);
        f1 += __shfl_xor_sync(0xffffffffu, f1, 16);
        f2 += __shfl_xor_sync(0xffffffffu, f2, 16);
        f3 += __shfl_xor_sync(0xffffffffu, f3, 16);
        if (lane < 16)
            ((float4*)out)[(size_t)sset * 16 + j] = make_float4(f0, f1, f2, f3);
    }

    // ---------------- per-sample metadata ----------------
    int n = sset * NSAMP + lane;
    int seg = __ldg(&idx[n]);
    float2 t = __ldg(&tr[n]);
    float t0v = fmaxf(fmaf(t.x, g_c0[0], fmaf(t.y, g_c0[1], g_c0[2])), 0.f);
    float t1v = fmaxf(fmaf(t.x, g_c1[0], fmaf(t.y, g_c1[1], g_c1[2])), 0.f);

    __syncwarp();

    // ---------------- dual (q,v) dot products ----------------
    unsigned long long acc[MID];
    #pragma unroll
    for (int m = 0; m < MID; m++) acc[m] = 0ull;

    const float* row = sX[warp] + lane * 64;       // lane = sample
    const int lx = lane & 7;
    const ulonglong2* sWu = (const ulonglong2*)sW; // [m][32]: 2 (wq,wv) pairs each

    #pragma unroll
    for (int c = 0; c < 16; c++) {
        float4 a0 = *(const float4*)&row[(c ^ lx) * 4];  // conflict-free (swizzle)
        unsigned long long x0 = pk2(a0.x, a0.x), x1 = pk2(a0.y, a0.y);
        unsigned long long x2 = pk2(a0.z, a0.z), x3 = pk2(a0.w, a0.w);
        #pragma unroll
        for (int m = 0; m < MID; m++) {
            ulonglong2 wA = sWu[m * 32 + 2 * c];        // (q,v) for k=4c,4c+1
            ulonglong2 wB = sWu[m * 32 + 2 * c + 1];    // (q,v) for k=4c+2,4c+3
            fma2(acc[m], x0, wA.x); fma2(acc[m], x1, wA.y);
            fma2(acc[m], x2, wB.x); fma2(acc[m], x3, wB.y);
        }
    }

    // ---------------- epilogue: exp + scatter RED ----------------
    float ev[MID], rv[MID];
    #pragma unroll
    for (int m = 0; m < MID; m++) {
        float2 a = upk2(acc[m]);
        float qm = a.x + g_bq[m] + t0v * g_A[m][0] + t1v * g_A[m][1];
        float vm = a.y + __ldg(&bv[m]);
        float em = __expf(qm);              // |q| is O(1): no max-subtraction needed
        ev[m] = em;
        rv[m] = vm * em;
    }
    float4* base = g_buf4 + (size_t)seg * 4;
    red4(base + 0, ev[0], ev[1], ev[2], ev[3]);
    red4(base + 1, ev[4], ev[5], ev[6], ev[7]);
    red4(base + 2, rv[0], rv[1], rv[2], rv[3]);
    red4(base + 3, rv[4], rv[5], rv[6], rv[7]);
}

// ---------------- K4: out = features + tile(res/gsum, 8); re-zero g_buf4 ----------------
// Block of 256 covers exactly 16 sets (16 float4 each) -> same-block read/zero with sync.
__global__ void k_final(float* __restrict__ out, int total4) {
    int i = blockIdx.x * blockDim.x + threadIdx.x;
    bool ok = i < total4;
    int s = i >> 4;
    int h = i & 1;
    float4 gs, rs, o;
    if (ok) {
        gs = g_buf4[s * 4 + h];
        rs = g_buf4[s * 4 + 2 + h];
        o  = ((float4*)out)[i];
    }
    __syncthreads();
    if (ok && (i & 15) < 4)
        g_buf4[s * 4 + (i & 15)] = make_float4(0.f, 0.f, 0.f, 0.f);  // zero-invariant
    if (ok) {
        o.x += rs.x / gs.x;
        o.y += rs.y / gs.y;
        o.z += rs.z / gs.z;
        o.w += rs.w / gs.w;
        ((float4*)out)[i] = o;
    }
}

// ---------------- launch ----------------
extern "C" void kernel_launch(void* const* d_in, const int* in_sizes, int n_in,
                              void* d_out, int out_size) {
    const float* outputs = (const float*)d_in[0];
    const float* transl  = (const float*)d_in[1];
    const int*   idx     = (const int*)  d_in[2];
    const float* Wq      = (const float*)d_in[3];
    const float* bq      = (const float*)d_in[4];
    const float* Wv      = (const float*)d_in[5];
    const float* bv      = (const float*)d_in[6];
    const float* Wp1     = (const float*)d_in[7];
    const float* gamma   = (const float*)d_in[8];
    const float* beta    = (const float*)d_in[9];
    const float* Wp2     = (const float*)d_in[10];
    const float* bp2     = (const float*)d_in[11];

    int N     = in_sizes[2];          // SIZE*NS
    int nsets = out_size / OUTP;      // SIZE

    k_stats<<<512, 256>>>((const float2*)transl, Wp1, N);
    k_prep <<<1, 32>>>(Wq, bq, Wp1, gamma, beta, Wp2, bp2, N);
    int blocks = (nsets + 3) / 4;     // 4 warps/block, 1 set/warp
    k_main <<<blocks, 128>>>((const float4*)outputs, (const float2*)transl,
                             idx, Wq, Wv, bv, (float*)d_out, nsets);
    k_final<<<(nsets * 16 + 255) / 256, 256>>>((float*)d_out, nsets * 16);
}

// round 9
// speedup vs baseline: 1.2206x; 1.2206x over previous
#include <cuda_runtime.h>

#define NSAMP 32
#define OUTP  64
#define MID   8
#define MAXSETS 50000

// ---------------- device scratch (zero-initialized at module load) ----------------
__device__ double g_stats[4];              // k_prep re-zeroes after reading
__device__ float  g_c0[3];                 // t0 = tr.x*c0[0] + tr.y*c0[1] + c0[2]
__device__ float  g_c1[3];
__device__ float  g_A[MID][2];             // folded relu(t) -> q coupling
__device__ float  g_bq[MID];               // b_q + Wq . b_p2
__device__ float4 g_buf4[MAXSETS * 4];     // per set: [gsum(8) | res(8)]; k_final re-zeroes

// ---------------- packed f32x2 helpers ----------------
__device__ __forceinline__ void fma2(unsigned long long &d, unsigned long long a, unsigned long long b) {
    asm("fma.rn.f32x2 %0, %1, %2, %0;" : "+l"(d) : "l"(a), "l"(b));
}
__device__ __forceinline__ float2 upk2(unsigned long long a) {
    float2 r;
    asm("mov.b64 {%0,%1}, %2;" : "=f"(r.x), "=f"(r.y) : "l"(a));
    return r;
}
__device__ __forceinline__ void red2(float* p, float a, float b) {
    asm volatile("red.global.add.v2.f32 [%0], {%1,%2};"
                 :: "l"(p), "f"(a), "f"(b) : "memory");
}

// ---------------- K1: BatchNorm batch statistics over t = tr @ Wp1^T ----------------
__global__ void k_stats(const float2* __restrict__ tr, const float* __restrict__ Wp1, int N) {
    float w00 = __ldg(Wp1 + 0), w01 = __ldg(Wp1 + 1);
    float w10 = __ldg(Wp1 + 2), w11 = __ldg(Wp1 + 3);
    float s0 = 0.f, s1 = 0.f, q0 = 0.f, q1 = 0.f;
    for (int n = blockIdx.x * blockDim.x + threadIdx.x; n < N; n += gridDim.x * blockDim.x) {
        float2 t = __ldg(&tr[n]);
        float t0 = t.x * w00 + t.y * w01;
        float t1 = t.x * w10 + t.y * w11;
        s0 += t0; s1 += t1; q0 += t0 * t0; q1 += t1 * t1;
    }
    #pragma unroll
    for (int o = 16; o; o >>= 1) {
        s0 += __shfl_xor_sync(0xffffffffu, s0, o);
        s1 += __shfl_xor_sync(0xffffffffu, s1, o);
        q0 += __shfl_xor_sync(0xffffffffu, q0, o);
        q1 += __shfl_xor_sync(0xffffffffu, q1, o);
    }
    if ((threadIdx.x & 31) == 0) {
        atomicAdd(&g_stats[0], (double)s0);
        atomicAdd(&g_stats[1], (double)s1);
        atomicAdd(&g_stats[2], (double)q0);
        atomicAdd(&g_stats[3], (double)q1);
    }
}

// ---------------- K2: fold BN + p-branch into small constants (re-zero g_stats) -------
__global__ void k_prep(const float* __restrict__ Wq, const float* __restrict__ bq,
                       const float* __restrict__ Wp1, const float* __restrict__ gamma,
                       const float* __restrict__ beta, const float* __restrict__ Wp2,
                       const float* __restrict__ bp2, int N) {
    int t = threadIdx.x;
    if (t < 2) {
        double mean = g_stats[t] / (double)N;
        double var  = g_stats[2 + t] / (double)N - mean * mean;
        float sc = gamma[t] / sqrtf((float)var + 1e-5f);
        float* c = t ? g_c1 : g_c0;
        c[0] = Wp1[t * 2 + 0] * sc;
        c[1] = Wp1[t * 2 + 1] * sc;
        c[2] = beta[t] - (float)mean * sc;
    }
    if (t < MID) {
        float a0 = 0.f, a1 = 0.f, bb = bq[t];
        for (int k = 0; k < OUTP; k++) {
            float w = Wq[t * OUTP + k];
            a0 += w * Wp2[k * 2 + 0];
            a1 += w * Wp2[k * 2 + 1];
            bb += w * bp2[k];
        }
        g_A[t][0] = a0; g_A[t][1] = a1; g_bq[t] = bb;
    }
    __syncwarp();
    if (t < 4) g_stats[t] = 0.0;   // restore zero-invariant for next replay
}

// ---------------- K3: fused main pass ----------------
// Block = 128 (4 warps), 1 set per warp. Lane = (mg = lane>>3, r = lane&7):
// lane computes m-pair {2mg,2mg+1} for rows {r, r+8, r+16, r+24}.
// Weight LDS: 4 distinct addrs/instr (8-way bcast)   -> 1 wf
// Data  LDS: 8 swizzled rows x 16B = 128B            -> 1 wf
__global__ void __launch_bounds__(128) k_main(
    const float4* __restrict__ x, const float2* __restrict__ tr,
    const int* __restrict__ idx, const float* __restrict__ Wq,
    const float* __restrict__ Wv, const float* __restrict__ bv,
    float* __restrict__ out, int nsets)
{
    // sW[m][j] = (Wq[m][2j], Wq[m][2j+1] | Wv[m][2j], Wv[m][2j+1]); row padded to 33
    __shared__ float4 sW[MID][33];
    __shared__ float  sX[4][NSAMP * OUTP];       // 32KB: [warp][sample*64 swizzled]

    int tid = threadIdx.x;
    #pragma unroll
    for (int i = tid; i < MID * 32; i += 128) {
        int m = i >> 5, j = i & 31;
        sW[m][j] = make_float4(__ldg(&Wq[m * OUTP + 2 * j]), __ldg(&Wq[m * OUTP + 2 * j + 1]),
                               __ldg(&Wv[m * OUTP + 2 * j]), __ldg(&Wv[m * OUTP + 2 * j + 1]));
    }
    __syncthreads();

    int warp = tid >> 5, lane = tid & 31;
    int sset = blockIdx.x * 4 + warp;
    if (sset >= nsets) return;                   // uniform per warp; no later __syncthreads

    // ---------------- staging + features (coalesced) ----------------
    int half = lane >> 4;          // sample parity this lane loads
    int j    = lane & 15;          // float4 group (channels 4j..4j+3)
    {
        const float4* src = x + (size_t)sset * NSAMP * 16;
        float* dst = sX[warp];
        float f0 = 0.f, f1 = 0.f, f2 = 0.f, f3 = 0.f;
        #pragma unroll
        for (int it = 0; it < 16; it++) {
            int s = it * 2 + half;
            float4 v = __ldg(&src[s * 16 + j]);  // warp: 512B contiguous
            f0 += v.x; f1 += v.y; f2 += v.z; f3 += v.w;
            int jp = j ^ (s & 7);                // XOR swizzle
            *(float4*)&dst[s * 64 + jp * 4] = v;
        }
        f0 += __shfl_xor_sync(0xffffffffu, f0, 16);
        f1 += __shfl_xor_sync(0xffffffffu, f1, 16);
        f2 += __shfl_xor_sync(0xffffffffu, f2, 16);
        f3 += __shfl_xor_sync(0xffffffffu, f3, 16);
        if (lane < 16)
            ((float4*)out)[(size_t)sset * 16 + j] = make_float4(f0, f1, f2, f3);
    }

    // ---------------- per-sample metadata (lane = row) ----------------
    int n = sset * NSAMP + lane;
    int seg = __ldg(&idx[n]);
    float2 t = __ldg(&tr[n]);
    float t0v = fmaxf(fmaf(t.x, g_c0[0], fmaf(t.y, g_c0[1], g_c0[2])), 0.f);
    float t1v = fmaxf(fmaf(t.x, g_c1[0], fmaf(t.y, g_c1[1], g_c1[2])), 0.f);

    __syncwarp();

    // ---------------- dual (q,v) dots: m-pair per lane, 4 rows per lane ----------------
    const int r  = lane & 7;
    const int m0 = (lane >> 3) << 1;             // 2*mg

    unsigned long long accq[4][2], accv[4][2];   // [row-block][m within pair]
    #pragma unroll
    for (int b = 0; b < 4; b++) { accq[b][0] = accq[b][1] = accv[b][0] = accv[b][1] = 0ull; }

    const float* base = sX[warp];
    #pragma unroll
    for (int c = 0; c < 16; c++) {
        ulonglong2 w0 = *(const ulonglong2*)&sW[m0][2 * c];        // m0: (q-pair | v-pair) k=4c,4c+1
        ulonglong2 w0b = *(const ulonglong2*)&sW[m0][2 * c + 1];   // m0: k=4c+2,4c+3
        ulonglong2 w1 = *(const ulonglong2*)&sW[m0 + 1][2 * c];
        ulonglong2 w1b = *(const ulonglong2*)&sW[m0 + 1][2 * c + 1];
        #pragma unroll
        for (int b = 0; b < 4; b++) {
            // stored group (c^row)^row = c -> channels 4c..4c+3 of row 8b+r
            ulonglong2 d = *(const ulonglong2*)&base[(8 * b + r) * 64 + ((c ^ r) << 2)];
            fma2(accq[b][0], d.x, w0.x);  fma2(accv[b][0], d.x, w0.y);
            fma2(accq[b][0], d.y, w0b.x); fma2(accv[b][0], d.y, w0b.y);
            fma2(accq[b][1], d.x, w1.x);  fma2(accv[b][1], d.x, w1.y);
            fma2(accq[b][1], d.y, w1b.x); fma2(accv[b][1], d.y, w1b.y);
        }
    }

    // ---------------- epilogue: exp + scatter RED (v2) ----------------
    float bv0 = __ldg(&bv[m0]), bv1 = __ldg(&bv[m0 + 1]);
    float A00 = g_A[m0][0], A01 = g_A[m0][1], A10 = g_A[m0 + 1][0], A11 = g_A[m0 + 1][1];
    float bq0 = g_bq[m0], bq1 = g_bq[m0 + 1];
    float* gf = (float*)g_buf4;
    #pragma unroll
    for (int b = 0; b < 4; b++) {
        int row = 8 * b + r;
        float t0b = __shfl_sync(0xffffffffu, t0v, row);
        float t1b = __shfl_sync(0xffffffffu, t1v, row);
        int   sgb = __shfl_sync(0xffffffffu, seg, row);
        float2 aq0 = upk2(accq[b][0]), av0 = upk2(accv[b][0]);
        float2 aq1 = upk2(accq[b][1]), av1 = upk2(accv[b][1]);
        float q0 = aq0.x + aq0.y + bq0 + t0b * A00 + t1b * A01;
        float q1 = aq1.x + aq1.y + bq1 + t0b * A10 + t1b * A11;
        float v0 = av0.x + av0.y + bv0;
        float v1 = av1.x + av1.y + bv1;
        float e0 = __expf(q0), e1 = __expf(q1);   // |q| is O(1): no max-subtraction
        float* p = gf + (size_t)sgb * 16 + m0;
        red2(p,     e0,      e1);
        red2(p + 8, v0 * e0, v1 * e1);
    }
}

// ---------------- K4: out = features + tile(res/gsum, 8); re-zero g_buf4 ----------------
// Block of 256 covers exactly 16 sets (16 float4 each) -> same-block read/zero with sync.
__global__ void k_final(float* __restrict__ out, int total4) {
    int i = blockIdx.x * blockDim.x + threadIdx.x;
    bool ok = i < total4;
    int s = i >> 4;
    int h = i & 1;
    float4 gs, rs, o;
    if (ok) {
        gs = g_buf4[s * 4 + h];
        rs = g_buf4[s * 4 + 2 + h];
        o  = ((float4*)out)[i];
    }
    __syncthreads();
    if (ok && (i & 15) < 4)
        g_buf4[s * 4 + (i & 15)] = make_float4(0.f, 0.f, 0.f, 0.f);  // zero-invariant
    if (ok) {
        o.x += rs.x / gs.x;
        o.y += rs.y / gs.y;
        o.z += rs.z / gs.z;
        o.w += rs.w / gs.w;
        ((float4*)out)[i] = o;
    }
}

// ---------------- launch ----------------
extern "C" void kernel_launch(void* const* d_in, const int* in_sizes, int n_in,
                              void* d_out, int out_size) {
    const float* outputs = (const float*)d_in[0];
    const float* transl  = (const float*)d_in[1];
    const int*   idx     = (const int*)  d_in[2];
    const float* Wq      = (const float*)d_in[3];
    const float* bq      = (const float*)d_in[4];
    const float* Wv      = (const float*)d_in[5];
    const float* bv      = (const float*)d_in[6];
    const float* Wp1     = (const float*)d_in[7];
    const float* gamma   = (const float*)d_in[8];
    const float* beta    = (const float*)d_in[9];
    const float* Wp2     = (const float*)d_in[10];
    const float* bp2     = (const float*)d_in[11];

    int N     = in_sizes[2];          // SIZE*NS
    int nsets = out_size / OUTP;      // SIZE

    k_stats<<<512, 256>>>((const float2*)transl, Wp1, N);
    k_prep <<<1, 32>>>(Wq, bq, Wp1, gamma, beta, Wp2, bp2, N);
    int blocks = (nsets + 3) / 4;     // 4 warps/block, 1 set/warp
    k_main <<<blocks, 128>>>((const float4*)outputs, (const float2*)transl,
                             idx, Wq, Wv, bv, (float*)d_out, nsets);
    k_final<<<(nsets * 16 + 255) / 256, 256>>>((float*)d_out, nsets * 16);
}

// round 10
// speedup vs baseline: 1.4246x; 1.1672x over previous
#include <cuda_runtime.h>
#include <cstdint>

#define NSAMP 32
#define OUTP  64
#define MID   8
#define MAXSETS 50000

// ---------------- device scratch (zero-initialized at module load) ----------------
__device__ double g_stats[4];              // k_prep re-zeroes after reading
__device__ float  g_c0[3];                 // t0 = tr.x*c0[0] + tr.y*c0[1] + c0[2]
__device__ float  g_c1[3];
__device__ float  g_A[MID][2];             // folded relu(t) -> q coupling
__device__ float  g_bq[MID];               // b_q + Wq . b_p2
__device__ float4 g_buf4[MAXSETS * 4];     // per set: [gsum(8) | res(8)]; k_final re-zeroes

__device__ __forceinline__ void red2(float* p, float a, float b) {
    asm volatile("red.global.add.v2.f32 [%0], {%1,%2};"
                 :: "l"(p), "f"(a), "f"(b) : "memory");
}

// tf32 MMA: D[16x8] += A[16x8] @ B[8x8] (row.col). Raw f32 bits: HW truncates to tf32.
#define MMA_TF32(d0,d1,d2,d3, a0,a1,a2,a3, b0,b1) \
    asm("mma.sync.aligned.m16n8k8.row.col.f32.tf32.tf32.f32 " \
        "{%0,%1,%2,%3}, {%4,%5,%6,%7}, {%8,%9}, {%0,%1,%2,%3};" \
        : "+f"(d0), "+f"(d1), "+f"(d2), "+f"(d3) \
        : "r"(a0), "r"(a1), "r"(a2), "r"(a3), "r"(b0), "r"(b1))

// ---------------- K1: BatchNorm batch statistics over t = tr @ Wp1^T ----------------
__global__ void k_stats(const float2* __restrict__ tr, const float* __restrict__ Wp1, int N) {
    float w00 = __ldg(Wp1 + 0), w01 = __ldg(Wp1 + 1);
    float w10 = __ldg(Wp1 + 2), w11 = __ldg(Wp1 + 3);
    float s0 = 0.f, s1 = 0.f, q0 = 0.f, q1 = 0.f;
    for (int n = blockIdx.x * blockDim.x + threadIdx.x; n < N; n += gridDim.x * blockDim.x) {
        float2 t = __ldg(&tr[n]);
        float t0 = t.x * w00 + t.y * w01;
        float t1 = t.x * w10 + t.y * w11;
        s0 += t0; s1 += t1; q0 += t0 * t0; q1 += t1 * t1;
    }
    #pragma unroll
    for (int o = 16; o; o >>= 1) {
        s0 += __shfl_xor_sync(0xffffffffu, s0, o);
        s1 += __shfl_xor_sync(0xffffffffu, s1, o);
        q0 += __shfl_xor_sync(0xffffffffu, q0, o);
        q1 += __shfl_xor_sync(0xffffffffu, q1, o);
    }
    if ((threadIdx.x & 31) == 0) {
        atomicAdd(&g_stats[0], (double)s0);
        atomicAdd(&g_stats[1], (double)s1);
        atomicAdd(&g_stats[2], (double)q0);
        atomicAdd(&g_stats[3], (double)q1);
    }
}

// ---------------- K2: fold BN + p-branch into small constants (re-zero g_stats) -------
__global__ void k_prep(const float* __restrict__ Wq, const float* __restrict__ bq,
                       const float* __restrict__ Wp1, const float* __restrict__ gamma,
                       const float* __restrict__ beta, const float* __restrict__ Wp2,
                       const float* __restrict__ bp2, int N) {
    int t = threadIdx.x;
    if (t < 2) {
        double mean = g_stats[t] / (double)N;
        double var  = g_stats[2 + t] / (double)N - mean * mean;
        float sc = gamma[t] / sqrtf((float)var + 1e-5f);
        float* c = t ? g_c1 : g_c0;
        c[0] = Wp1[t * 2 + 0] * sc;
        c[1] = Wp1[t * 2 + 1] * sc;
        c[2] = beta[t] - (float)mean * sc;
    }
    if (t < MID) {
        float a0 = 0.f, a1 = 0.f, bb = bq[t];
        for (int k = 0; k < OUTP; k++) {
            float w = Wq[t * OUTP + k];
            a0 += w * Wp2[k * 2 + 0];
            a1 += w * Wp2[k * 2 + 1];
            bb += w * bp2[k];
        }
        g_A[t][0] = a0; g_A[t][1] = a1; g_bq[t] = bb;
    }
    __syncwarp();
    if (t < 4) g_stats[t] = 0.0;   // restore zero-invariant for next replay
}

// ---------------- K3: fused main pass (tf32 MMA) ----------------
// Block = 128 (4 warps), 1 set per warp.  Per-set GEMM: x[32x64] @ [Wq;Wv]^T[64x16]
// via 2 Mtiles x 2 Ntiles x 8 kc of mma.m16n8k8.tf32.
// k-permutation: matrix col j <-> k = 2j (j<4) / 2(j-4)+1, so A-frag (a0,a2) and
// B-frag (b0,b1) are ADJACENT k -> plain LDS.64 fragment loads.
// smem layouts (float2 "pair" units, pair p = k>>1, swizzle p ^= (row&7)<<2):
//   sX[warp]: 32 rows x 32 pairs;  sWf: 16 n-rows x 32 pairs.
__global__ void __launch_bounds__(128) k_main(
    const float4* __restrict__ x, const float2* __restrict__ tr,
    const int* __restrict__ idx, const float* __restrict__ Wq,
    const float* __restrict__ Wv, const float* __restrict__ bv,
    float* __restrict__ out, int nsets)
{
    __shared__ float2 sWf[16 * 32];              // 4KB: [n][pair] swizzled
    __shared__ float2 sX[4][NSAMP * 32];         // 32KB: [warp][row*32 + pair] swizzled

    int tid = threadIdx.x;
    #pragma unroll
    for (int i = tid; i < 16 * 32; i += 128) {
        int nr = i >> 5, p = i & 31;
        const float* Wsrc = (nr < 8) ? (Wq + nr * OUTP) : (Wv + (nr - 8) * OUTP);
        sWf[nr * 32 + (p ^ ((nr & 7) << 2))] =
            make_float2(__ldg(&Wsrc[2 * p]), __ldg(&Wsrc[2 * p + 1]));
    }
    __syncthreads();

    int warp = tid >> 5, lane = tid & 31;
    int sset = blockIdx.x * 4 + warp;
    if (sset >= nsets) return;                   // uniform per warp

    // ---------------- staging + features (coalesced LDG) ----------------
    int half = lane >> 4;          // sample parity this lane loads
    int j    = lane & 15;          // float4 group (pairs 2j, 2j+1)
    {
        const float4* src = x + (size_t)sset * NSAMP * 16;
        float2* dst = sX[warp];
        float f0 = 0.f, f1 = 0.f, f2 = 0.f, f3 = 0.f;
        #pragma unroll
        for (int it = 0; it < 16; it++) {
            int s = it * 2 + half;
            float4 v = __ldg(&src[s * 16 + j]);  // warp: 512B contiguous
            f0 += v.x; f1 += v.y; f2 += v.z; f3 += v.w;
            int pp = (2 * j) ^ ((s & 7) << 2);   // pair-swizzle (bit0 stays 0)
            *(float4*)&dst[s * 32 + pp] = v;
        }
        f0 += __shfl_xor_sync(0xffffffffu, f0, 16);
        f1 += __shfl_xor_sync(0xffffffffu, f1, 16);
        f2 += __shfl_xor_sync(0xffffffffu, f2, 16);
        f3 += __shfl_xor_sync(0xffffffffu, f3, 16);
        if (lane < 16)
            ((float4*)out)[(size_t)sset * 16 + j] = make_float4(f0, f1, f2, f3);
    }

    // ---------------- per-sample metadata (lane = row) ----------------
    int n = sset * NSAMP + lane;
    int seg = __ldg(&idx[n]);
    float2 t = __ldg(&tr[n]);
    float t0v = fmaxf(fmaf(t.x, g_c0[0], fmaf(t.y, g_c0[1], g_c0[2])), 0.f);
    float t1v = fmaxf(fmaf(t.x, g_c1[0], fmaf(t.y, g_c1[1], g_c1[2])), 0.f);

    __syncwarp();

    // ---------------- MMA mainloop ----------------
    const int g = lane >> 2, c = lane & 3;
    const int sw = g << 2;
    float dq[2][4], dv[2][4];
    #pragma unroll
    for (int mt = 0; mt < 2; mt++)
        #pragma unroll
        for (int i = 0; i < 4; i++) { dq[mt][i] = 0.f; dv[mt][i] = 0.f; }

    const float2* Xw = sX[warp];
    #pragma unroll
    for (int kc = 0; kc < 8; kc++) {
        int pidx = (kc * 4 + c) ^ sw;
        uint2 r0  = *(const uint2*)&Xw[(g)      * 32 + pidx];   // row g     pair
        uint2 r8  = *(const uint2*)&Xw[(g + 8)  * 32 + pidx];
        uint2 r16 = *(const uint2*)&Xw[(g + 16) * 32 + pidx];
        uint2 r24 = *(const uint2*)&Xw[(g + 24) * 32 + pidx];
        uint2 wq_ = *(const uint2*)&sWf[(g)     * 32 + pidx];   // Ntile0 = q
        uint2 wv_ = *(const uint2*)&sWf[(g + 8) * 32 + pidx];   // Ntile1 = v

        // Mtile0 (rows 0-15): frag {rg.x, rg8.x, rg.y, rg8.y}
        MMA_TF32(dq[0][0], dq[0][1], dq[0][2], dq[0][3], r0.x, r8.x, r0.y, r8.y, wq_.x, wq_.y);
        MMA_TF32(dv[0][0], dv[0][1], dv[0][2], dv[0][3], r0.x, r8.x, r0.y, r8.y, wv_.x, wv_.y);
        // Mtile1 (rows 16-31)
        MMA_TF32(dq[1][0], dq[1][1], dq[1][2], dq[1][3], r16.x, r24.x, r16.y, r24.y, wq_.x, wq_.y);
        MMA_TF32(dv[1][0], dv[1][1], dv[1][2], dv[1][3], r16.x, r24.x, r16.y, r24.y, wv_.x, wv_.y);
    }

    // ---------------- epilogue: exp + scatter RED (v2) ----------------
    // D layout: d0,d1 = row g cols (2c, 2c+1); d2,d3 = row g+8. b-th row = g + 8b.
    const int m0 = c << 1;
    float bq0 = g_bq[m0], bq1 = g_bq[m0 + 1];
    float A00 = g_A[m0][0], A01 = g_A[m0][1], A10 = g_A[m0 + 1][0], A11 = g_A[m0 + 1][1];
    float bv0 = __ldg(&bv[m0]), bv1 = __ldg(&bv[m0 + 1]);
    float* gf = (float*)g_buf4;
    #pragma unroll
    for (int b = 0; b < 4; b++) {
        int row = g + 8 * b;
        float t0b = __shfl_sync(0xffffffffu, t0v, row);
        float t1b = __shfl_sync(0xffffffffu, t1v, row);
        int   sgb = __shfl_sync(0xffffffffu, seg, row);
        int mt = b >> 1, hi = (b & 1) << 1;
        float q0 = dq[mt][hi]     + bq0 + t0b * A00 + t1b * A01;
        float q1 = dq[mt][hi + 1] + bq1 + t0b * A10 + t1b * A11;
        float v0 = dv[mt][hi]     + bv0;
        float v1 = dv[mt][hi + 1] + bv1;
        float e0 = __expf(q0), e1 = __expf(q1);   // |q| is O(1): no max-subtraction
        float* p = gf + (size_t)sgb * 16 + m0;
        red2(p,     e0,      e1);
        red2(p + 8, v0 * e0, v1 * e1);
    }
}

// ---------------- K4: out = features + tile(res/gsum, 8); re-zero g_buf4 ----------------
// Block of 256 covers exactly 16 sets (16 float4 each) -> same-block read/zero with sync.
__global__ void k_final(float* __restrict__ out, int total4) {
    int i = blockIdx.x * blockDim.x + threadIdx.x;
    bool ok = i < total4;
    int s = i >> 4;
    int h = i & 1;
    float4 gs, rs, o;
    if (ok) {
        gs = g_buf4[s * 4 + h];
        rs = g_buf4[s * 4 + 2 + h];
        o  = ((float4*)out)[i];
    }
    __syncthreads();
    if (ok && (i & 15) < 4)
        g_buf4[s * 4 + (i & 15)] = make_float4(0.f, 0.f, 0.f, 0.f);  // zero-invariant
    if (ok) {
        o.x += rs.x / gs.x;
        o.y += rs.y / gs.y;
        o.z += rs.z / gs.z;
        o.w += rs.w / gs.w;
        ((float4*)out)[i] = o;
    }
}

// ---------------- launch ----------------
extern "C" void kernel_launch(void* const* d_in, const int* in_sizes, int n_in,
                              void* d_out, int out_size) {
    const float* outputs = (const float*)d_in[0];
    const float* transl  = (const float*)d_in[1];
    const int*   idx     = (const int*)  d_in[2];
    const float* Wq      = (const float*)d_in[3];
    const float* bq      = (const float*)d_in[4];
    const float* Wv      = (const float*)d_in[5];
    const float* bv      = (const float*)d_in[6];
    const float* Wp1     = (const float*)d_in[7];
    const float* gamma   = (const float*)d_in[8];
    const float* beta    = (const float*)d_in[9];
    const float* Wp2     = (const float*)d_in[10];
    const float* bp2     = (const float*)d_in[11];

    int N     = in_sizes[2];          // SIZE*NS
    int nsets = out_size / OUTP;      // SIZE

    k_stats<<<512, 256>>>((const float2*)transl, Wp1, N);
    k_prep <<<1, 32>>>(Wq, bq, Wp1, gamma, beta, Wp2, bp2, N);
    int blocks = (nsets + 3) / 4;     // 4 warps/block, 1 set/warp
    k_main <<<blocks, 128>>>((const float4*)outputs, (const float2*)transl,
                             idx, Wq, Wv, bv, (float*)d_out, nsets);
    k_final<<<(nsets * 16 + 255) / 256, 256>>>((float*)d_out, nsets * 16);
}

// round 13
// speedup vs baseline: 1.4670x; 1.0298x over previous
#include <cuda_runtime.h>
#include <cstdint>

#define NSAMP 32
#define OUTP  64
#define MID   8
#define MAXSETS 50000

// ---------------- device scratch (zero-initialized at module load) ----------------
__device__ double g_stats[4];              // k_prep re-zeroes after reading
__device__ float  g_c0[3];                 // t0 = tr.x*c0[0] + tr.y*c0[1] + c0[2]
__device__ float  g_c1[3];
__device__ float  g_A[MID][2];             // folded relu(t) -> q coupling
__device__ float  g_bq[MID];               // b_q + Wq . b_p2
__device__ float4 g_buf4[MAXSETS * 4];     // per set: [gsum(8) | res(8)]; k_final re-zeroes

__device__ __forceinline__ void red4(float* p, float a, float b, float c, float d) {
    asm volatile("red.global.add.v4.f32 [%0], {%1,%2,%3,%4};"
                 :: "l"(p), "f"(a), "f"(b), "f"(c), "f"(d) : "memory");
}

// tf32 MMA: D[16x8] += A[16x8] @ B[8x8] (row.col). Raw f32 bits: HW truncates to tf32.
#define MMA_TF32(d0,d1,d2,d3, a0,a1,a2,a3, b0,b1) \
    asm("mma.sync.aligned.m16n8k8.row.col.f32.tf32.tf32.f32 " \
        "{%0,%1,%2,%3}, {%4,%5,%6,%7}, {%8,%9}, {%0,%1,%2,%3};" \
        : "+f"(d0), "+f"(d1), "+f"(d2), "+f"(d3) \
        : "r"(a0), "r"(a1), "r"(a2), "r"(a3), "r"(b0), "r"(b1))

// ---------------- K1: BatchNorm batch statistics over t = tr @ Wp1^T ----------------
__global__ void k_stats(const float2* __restrict__ tr, const float* __restrict__ Wp1, int N) {
    float w00 = __ldg(Wp1 + 0), w01 = __ldg(Wp1 + 1);
    float w10 = __ldg(Wp1 + 2), w11 = __ldg(Wp1 + 3);
    float s0 = 0.f, s1 = 0.f, q0 = 0.f, q1 = 0.f;
    for (int n = blockIdx.x * blockDim.x + threadIdx.x; n < N; n += gridDim.x * blockDim.x) {
        float2 t = __ldg(&tr[n]);
        float t0 = t.x * w00 + t.y * w01;
        float t1 = t.x * w10 + t.y * w11;
        s0 += t0; s1 += t1; q0 += t0 * t0; q1 += t1 * t1;
    }
    #pragma unroll
    for (int o = 16; o; o >>= 1) {
        s0 += __shfl_xor_sync(0xffffffffu, s0, o);
        s1 += __shfl_xor_sync(0xffffffffu, s1, o);
        q0 += __shfl_xor_sync(0xffffffffu, q0, o);
        q1 += __shfl_xor_sync(0xffffffffu, q1, o);
    }
    if ((threadIdx.x & 31) == 0) {
        atomicAdd(&g_stats[0], (double)s0);
        atomicAdd(&g_stats[1], (double)s1);
        atomicAdd(&g_stats[2], (double)q0);
        atomicAdd(&g_stats[3], (double)q1);
    }
}

// ---------------- K2: fold BN + p-branch into small constants (re-zero g_stats) -------
__global__ void k_prep(const float* __restrict__ Wq, const float* __restrict__ bq,
                       const float* __restrict__ Wp1, const float* __restrict__ gamma,
                       const float* __restrict__ beta, const float* __restrict__ Wp2,
                       const float* __restrict__ bp2, int N) {
    int t = threadIdx.x;
    if (t < 2) {
        double mean = g_stats[t] / (double)N;
        double var  = g_stats[2 + t] / (double)N - mean * mean;
        float sc = gamma[t] / sqrtf((float)var + 1e-5f);
        float* c = t ? g_c1 : g_c0;
        c[0] = Wp1[t * 2 + 0] * sc;
        c[1] = Wp1[t * 2 + 1] * sc;
        c[2] = beta[t] - (float)mean * sc;
    }
    if (t < MID) {
        float a0 = 0.f, a1 = 0.f, bb = bq[t];
        for (int k = 0; k < OUTP; k++) {
            float w = Wq[t * OUTP + k];
            a0 += w * Wp2[k * 2 + 0];
            a1 += w * Wp2[k * 2 + 1];
            bb += w * bp2[k];
        }
        g_A[t][0] = a0; g_A[t][1] = a1; g_bq[t] = bb;
    }
    __syncwarp();
    if (t < 4) g_stats[t] = 0.0;   // restore zero-invariant for next replay
}

// ---------------- K3: fused main pass (tf32 MMA) ----------------
// Block = 128 (4 warps), 1 set per warp.  Per-set GEMM: x[32x64] @ [Wq;Wv]^T[64x16]
// via 2 Mtiles x 2 Ntiles x 8 kc of mma.m16n8k8.tf32.
// Epilogue: 4-SHFL pair-exchange assembles m0-3 / m4-7 quads, ONE red4 per b
// (even-c lanes: e-quad; odd-c lanes: v*e-quad) -> 4 RED instr/set instead of 8.
__global__ void __launch_bounds__(128) k_main(
    const float4* __restrict__ x, const float2* __restrict__ tr,
    const int* __restrict__ idx, const float* __restrict__ Wq,
    const float* __restrict__ Wv, const float* __restrict__ bv,
    float* __restrict__ out, int nsets)
{
    __shared__ float2 sWf[16 * 32];              // 4KB: [n][pair] swizzled
    __shared__ float2 sX[4][NSAMP * 32];         // 32KB: [warp][row*32 + pair] swizzled

    int tid = threadIdx.x;
    #pragma unroll
    for (int i = tid; i < 16 * 32; i += 128) {
        int nr = i >> 5, p = i & 31;
        const float* Wsrc = (nr < 8) ? (Wq + nr * OUTP) : (Wv + (nr - 8) * OUTP);
        sWf[nr * 32 + (p ^ ((nr & 7) << 2))] =
            make_float2(__ldg(&Wsrc[2 * p]), __ldg(&Wsrc[2 * p + 1]));
    }
    __syncthreads();

    int warp = tid >> 5, lane = tid & 31;
    int sset = blockIdx.x * 4 + warp;
    if (sset >= nsets) return;                   // uniform per warp

    // ---------------- staging + features (coalesced LDG) ----------------
    int half = lane >> 4;          // sample parity this lane loads
    int j    = lane & 15;          // float4 group (pairs 2j, 2j+1)
    {
        const float4* src = x + (size_t)sset * NSAMP * 16;
        float2* dst = sX[warp];
        float f0 = 0.f, f1 = 0.f, f2 = 0.f, f3 = 0.f;
        #pragma unroll
        for (int it = 0; it < 16; it++) {
            int s = it * 2 + half;
            float4 v = __ldg(&src[s * 16 + j]);  // warp: 512B contiguous
            f0 += v.x; f1 += v.y; f2 += v.z; f3 += v.w;
            int pp = (2 * j) ^ ((s & 7) << 2);   // pair-swizzle (bit0 stays 0)
            *(float4*)&dst[s * 32 + pp] = v;
        }
        f0 += __shfl_xor_sync(0xffffffffu, f0, 16);
        f1 += __shfl_xor_sync(0xffffffffu, f1, 16);
        f2 += __shfl_xor_sync(0xffffffffu, f2, 16);
        f3 += __shfl_xor_sync(0xffffffffu, f3, 16);
        if (lane < 16)
            ((float4*)out)[(size_t)sset * 16 + j] = make_float4(f0, f1, f2, f3);
    }

    // ---------------- per-sample metadata (lane = row) ----------------
    int n = sset * NSAMP + lane;
    int seg = __ldg(&idx[n]);
    float2 t = __ldg(&tr[n]);
    float t0v = fmaxf(fmaf(t.x, g_c0[0], fmaf(t.y, g_c0[1], g_c0[2])), 0.f);
    float t1v = fmaxf(fmaf(t.x, g_c1[0], fmaf(t.y, g_c1[1], g_c1[2])), 0.f);

    __syncwarp();

    // ---------------- MMA mainloop ----------------
    const int g = lane >> 2, c = lane & 3;
    const int sw = g << 2;
    float dq[2][4], dv[2][4];
    #pragma unroll
    for (int mt = 0; mt < 2; mt++)
        #pragma unroll
        for (int i = 0; i < 4; i++) { dq[mt][i] = 0.f; dv[mt][i] = 0.f; }

    const float2* Xw = sX[warp];
    #pragma unroll
    for (int kc = 0; kc < 8; kc++) {
        int pidx = (kc * 4 + c) ^ sw;
        uint2 r0  = *(const uint2*)&Xw[(g)      * 32 + pidx];   // row g     pair
        uint2 r8  = *(const uint2*)&Xw[(g + 8)  * 32 + pidx];
        uint2 r16 = *(const uint2*)&Xw[(g + 16) * 32 + pidx];
        uint2 r24 = *(const uint2*)&Xw[(g + 24) * 32 + pidx];
        uint2 wq_ = *(const uint2*)&sWf[(g)     * 32 + pidx];   // Ntile0 = q
        uint2 wv_ = *(const uint2*)&sWf[(g + 8) * 32 + pidx];   // Ntile1 = v

        MMA_TF32(dq[0][0], dq[0][1], dq[0][2], dq[0][3], r0.x, r8.x, r0.y, r8.y, wq_.x, wq_.y);
        MMA_TF32(dv[0][0], dv[0][1], dv[0][2], dv[0][3], r0.x, r8.x, r0.y, r8.y, wv_.x, wv_.y);
        MMA_TF32(dq[1][0], dq[1][1], dq[1][2], dq[1][3], r16.x, r24.x, r16.y, r24.y, wq_.x, wq_.y);
        MMA_TF32(dv[1][0], dv[1][1], dv[1][2], dv[1][3], r16.x, r24.x, r16.y, r24.y, wv_.x, wv_.y);
    }

    // ---------------- epilogue: exp + pair-exchange + single red4 per b ----------------
    // D layout: d0,d1 = row g cols (2c,2c+1); d2,d3 = row g+8. b-th row = g + 8b.
    const int m0 = c << 1;
    const int mb = (c >> 1) << 2;               // quad base: 0 or 4
    float bq0 = g_bq[m0], bq1 = g_bq[m0 + 1];
    float A00 = g_A[m0][0], A01 = g_A[m0][1], A10 = g_A[m0 + 1][0], A11 = g_A[m0 + 1][1];
    float bv0 = __ldg(&bv[m0]), bv1 = __ldg(&bv[m0 + 1]);
    const bool codd = (c & 1);
    float* gf = (float*)g_buf4;
    #pragma unroll
    for (int b = 0; b < 4; b++) {
        int row = g + 8 * b;
        float t0b = __shfl_sync(0xffffffffu, t0v, row);
        float t1b = __shfl_sync(0xffffffffu, t1v, row);
        int   sgb = __shfl_sync(0xffffffffu, seg, row);
        int mt = b >> 1, hi = (b & 1) << 1;
        float q0 = dq[mt][hi]     + bq0 + t0b * A00 + t1b * A01;
        float q1 = dq[mt][hi + 1] + bq1 + t0b * A10 + t1b * A11;
        float v0 = dv[mt][hi]     + bv0;
        float v1 = dv[mt][hi + 1] + bv1;
        float e0 = __expf(q0), e1 = __expf(q1);   // |q| is O(1): no max-subtraction
        float w0 = v0 * e0,    w1 = v1 * e1;
        // exchange with partner lane c^1 (same g)
        float ex0 = __shfl_xor_sync(0xffffffffu, e0, 1);
        float ex1 = __shfl_xor_sync(0xffffffffu, e1, 1);
        float wx0 = __shfl_xor_sync(0xffffffffu, w0, 1);
        float wx1 = __shfl_xor_sync(0xffffffffu, w1, 1);
        // even c: e-quad [m mb..mb+3]; odd c: w-quad at +8
        float a0 = codd ? wx0 : e0;
        float a1 = codd ? wx1 : e1;
        float a2 = codd ? w0  : ex0;
        float a3 = codd ? w1  : ex1;
        float* p = gf + (size_t)sgb * 16 + mb + (codd ? 8 : 0);
        red4(p, a0, a1, a2, a3);
    }
}

// ---------------- K4: out = features + tile(res/gsum, 8); re-zero g_buf4 ----------------
// Thread = (set, quarter r): loads gs/rs once, processes out float4s i0 and i0+2.
// 8 threads per set live in one warp (8 | 32) -> __syncwarp orders read-then-zero.
__global__ void k_final(float* __restrict__ out, int nsets) {
    int tid = blockIdx.x * blockDim.x + threadIdx.x;
    int s = tid >> 3, r = tid & 7;
    bool ok = s < nsets;
    float4 gs, rs, o0, o1;
    int i0 = 0;
    if (ok) {
        int h = r & 1;
        gs = g_buf4[s * 4 + h];
        rs = g_buf4[s * 4 + 2 + h];
        i0 = s * 16 + (r >> 1) * 4 + h;
        o0 = ((float4*)out)[i0];
        o1 = ((float4*)out)[i0 + 2];
    }
    __syncwarp();
    if (ok && r < 4)
        g_buf4[s * 4 + r] = make_float4(0.f, 0.f, 0.f, 0.f);  // zero-invariant
    if (ok) {
        float wx = rs.x / gs.x, wy = rs.y / gs.y, wz = rs.z / gs.z, ww = rs.w / gs.w;
        o0.x += wx; o0.y += wy; o0.z += wz; o0.w += ww;
        o1.x += wx; o1.y += wy; o1.z += wz; o1.w += ww;
        ((float4*)out)[i0]     = o0;
        ((float4*)out)[i0 + 2] = o1;
    }
}

// ---------------- launch ----------------
extern "C" void kernel_launch(void* const* d_in, const int* in_sizes, int n_in,
                              void* d_out, int out_size) {
    const float* outputs = (const float*)d_in[0];
    const float* transl  = (const float*)d_in[1];
    const int*   idx     = (const int*)  d_in[2];
    const float* Wq      = (const float*)d_in[3];
    const float* bq      = (const float*)d_in[4];
    const float* Wv      = (const float*)d_in[5];
    const float* bv      = (const float*)d_in[6];
    const float* Wp1     = (const float*)d_in[7];
    const float* gamma   = (const float*)d_in[8];
    const float* beta    = (const float*)d_in[9];
    const float* Wp2     = (const float*)d_in[10];
    const float* bp2     = (const float*)d_in[11];

    int N     = in_sizes[2];          // SIZE*NS
    int nsets = out_size / OUTP;      // SIZE

    k_stats<<<512, 256>>>((const float2*)transl, Wp1, N);
    k_prep <<<1, 32>>>(Wq, bq, Wp1, gamma, beta, Wp2, bp2, N);
    int blocks = (nsets + 3) / 4;     // 4 warps/block, 1 set/warp
    k_main <<<blocks, 128>>>((const float4*)outputs, (const float2*)transl,
                             idx, Wq, Wv, bv, (float*)d_out, nsets);
    k_final<<<(nsets * 8 + 255) / 256, 256>>>((float*)d_out, nsets);
}

// round 14
// speedup vs baseline: 1.6952x; 1.1556x over previous
#include <cuda_runtime.h>
#include <cstdint>

#define NSAMP 32
#define OUTP  64
#define MID   8
#define MAXSETS 50000

// ---------------- device scratch (zero-initialized at module load) ----------------
__device__ double g_stats[4];              // k_prep re-zeroes after reading
__device__ float  g_c0[3];                 // t0 = tr.x*c0[0] + tr.y*c0[1] + c0[2]
__device__ float  g_c1[3];
__device__ float  g_A[MID][2];             // folded relu(t) -> q coupling
__device__ float  g_bq[MID];               // b_q + Wq . b_p2
__device__ float4 g_buf4[MAXSETS * 4];     // per set: [gsum(8) | res(8)]; k_final re-zeroes

__device__ __forceinline__ void red4(float* p, float a, float b, float c, float d) {
    asm volatile("red.global.add.v4.f32 [%0], {%1,%2,%3,%4};"
                 :: "l"(p), "f"(a), "f"(b), "f"(c), "f"(d) : "memory");
}

// tf32 MMA: D[16x8] += A[16x8] @ B[8x8] (row.col). Raw f32 bits: HW truncates to tf32.
#define MMA_TF32(d0,d1,d2,d3, a0,a1,a2,a3, b0,b1) \
    asm("mma.sync.aligned.m16n8k8.row.col.f32.tf32.tf32.f32 " \
        "{%0,%1,%2,%3}, {%4,%5,%6,%7}, {%8,%9}, {%0,%1,%2,%3};" \
        : "+f"(d0), "+f"(d1), "+f"(d2), "+f"(d3) \
        : "r"(a0), "r"(a1), "r"(a2), "r"(a3), "r"(b0), "r"(b1))

// ---------------- K1: BN batch stats; block-reduced, 4 f64 atomics per BLOCK ----------
__global__ void k_stats(const float2* __restrict__ tr, const float* __restrict__ Wp1, int N) {
    __shared__ float4 sred[8];
    float w00 = __ldg(Wp1 + 0), w01 = __ldg(Wp1 + 1);
    float w10 = __ldg(Wp1 + 2), w11 = __ldg(Wp1 + 3);
    float s0 = 0.f, s1 = 0.f, q0 = 0.f, q1 = 0.f;
    for (int n = blockIdx.x * blockDim.x + threadIdx.x; n < N; n += gridDim.x * blockDim.x) {
        float2 t = __ldg(&tr[n]);
        float t0 = t.x * w00 + t.y * w01;
        float t1 = t.x * w10 + t.y * w11;
        s0 += t0; s1 += t1; q0 += t0 * t0; q1 += t1 * t1;
    }
    #pragma unroll
    for (int o = 16; o; o >>= 1) {
        s0 += __shfl_xor_sync(0xffffffffu, s0, o);
        s1 += __shfl_xor_sync(0xffffffffu, s1, o);
        q0 += __shfl_xor_sync(0xffffffffu, q0, o);
        q1 += __shfl_xor_sync(0xffffffffu, q1, o);
    }
    int warp = threadIdx.x >> 5, lane = threadIdx.x & 31;
    if (lane == 0) sred[warp] = make_float4(s0, s1, q0, q1);
    __syncthreads();
    if (warp == 0) {
        float4 v = (lane < 8) ? sred[lane] : make_float4(0.f, 0.f, 0.f, 0.f);
        #pragma unroll
        for (int o = 4; o; o >>= 1) {
            v.x += __shfl_xor_sync(0xffffffffu, v.x, o);
            v.y += __shfl_xor_sync(0xffffffffu, v.y, o);
            v.z += __shfl_xor_sync(0xffffffffu, v.z, o);
            v.w += __shfl_xor_sync(0xffffffffu, v.w, o);
        }
        if (lane == 0) {
            atomicAdd(&g_stats[0], (double)v.x);
            atomicAdd(&g_stats[1], (double)v.y);
            atomicAdd(&g_stats[2], (double)v.z);
            atomicAdd(&g_stats[3], (double)v.w);
        }
    }
}

// ---------------- K2: fold BN + p-branch; warp-per-m parallel dots -------------------
__global__ void k_prep(const float* __restrict__ Wq, const float* __restrict__ bq,
                       const float* __restrict__ Wp1, const float* __restrict__ gamma,
                       const float* __restrict__ beta, const float* __restrict__ Wp2,
                       const float* __restrict__ bp2, int N) {
    int tid = threadIdx.x;
    int m = tid >> 5, lane = tid & 31;
    // per-m dots over k, split across the warp (lane covers k=lane, lane+32)
    float a0 = 0.f, a1 = 0.f, bb = 0.f;
    #pragma unroll
    for (int h = 0; h < 2; h++) {
        int k = lane + 32 * h;
        float w = __ldg(&Wq[m * OUTP + k]);
        a0 += w * __ldg(&Wp2[k * 2 + 0]);
        a1 += w * __ldg(&Wp2[k * 2 + 1]);
        bb += w * __ldg(&bp2[k]);
    }
    #pragma unroll
    for (int o = 16; o; o >>= 1) {
        a0 += __shfl_xor_sync(0xffffffffu, a0, o);
        a1 += __shfl_xor_sync(0xffffffffu, a1, o);
        bb += __shfl_xor_sync(0xffffffffu, bb, o);
    }
    if (lane == 0) {
        g_A[m][0] = a0; g_A[m][1] = a1; g_bq[m] = bb + __ldg(&bq[m]);
    }
    if (tid < 2) {
        double mean = g_stats[tid] / (double)N;
        double var  = g_stats[2 + tid] / (double)N - mean * mean;
        float sc = gamma[tid] / sqrtf((float)var + 1e-5f);
        float* c = tid ? g_c1 : g_c0;
        c[0] = Wp1[tid * 2 + 0] * sc;
        c[1] = Wp1[tid * 2 + 1] * sc;
        c[2] = beta[tid] - (float)mean * sc;
    }
    __syncthreads();
    if (tid < 4) g_stats[tid] = 0.0;   // restore zero-invariant for next replay
}

// ---------------- K3: fused main pass (tf32 MMA) — unchanged from R13 ----------------
__global__ void __launch_bounds__(128) k_main(
    const float4* __restrict__ x, const float2* __restrict__ tr,
    const int* __restrict__ idx, const float* __restrict__ Wq,
    const float* __restrict__ Wv, const float* __restrict__ bv,
    float* __restrict__ out, int nsets)
{
    __shared__ float2 sWf[16 * 32];              // 4KB: [n][pair] swizzled
    __shared__ float2 sX[4][NSAMP * 32];         // 32KB: [warp][row*32 + pair] swizzled

    int tid = threadIdx.x;
    #pragma unroll
    for (int i = tid; i < 16 * 32; i += 128) {
        int nr = i >> 5, p = i & 31;
        const float* Wsrc = (nr < 8) ? (Wq + nr * OUTP) : (Wv + (nr - 8) * OUTP);
        sWf[nr * 32 + (p ^ ((nr & 7) << 2))] =
            make_float2(__ldg(&Wsrc[2 * p]), __ldg(&Wsrc[2 * p + 1]));
    }
    __syncthreads();

    int warp = tid >> 5, lane = tid & 31;
    int sset = blockIdx.x * 4 + warp;
    if (sset >= nsets) return;                   // uniform per warp

    // ---------------- staging + features (coalesced LDG) ----------------
    int half = lane >> 4;          // sample parity this lane loads
    int j    = lane & 15;          // float4 group (pairs 2j, 2j+1)
    {
        const float4* src = x + (size_t)sset * NSAMP * 16;
        float2* dst = sX[warp];
        float f0 = 0.f, f1 = 0.f, f2 = 0.f, f3 = 0.f;
        #pragma unroll
        for (int it = 0; it < 16; it++) {
            int s = it * 2 + half;
            float4 v = __ldg(&src[s * 16 + j]);  // warp: 512B contiguous
            f0 += v.x; f1 += v.y; f2 += v.z; f3 += v.w;
            int pp = (2 * j) ^ ((s & 7) << 2);   // pair-swizzle (bit0 stays 0)
            *(float4*)&dst[s * 32 + pp] = v;
        }
        f0 += __shfl_xor_sync(0xffffffffu, f0, 16);
        f1 += __shfl_xor_sync(0xffffffffu, f1, 16);
        f2 += __shfl_xor_sync(0xffffffffu, f2, 16);
        f3 += __shfl_xor_sync(0xffffffffu, f3, 16);
        if (lane < 16)
            ((float4*)out)[(size_t)sset * 16 + j] = make_float4(f0, f1, f2, f3);
    }

    // ---------------- per-sample metadata (lane = row) ----------------
    int n = sset * NSAMP + lane;
    int seg = __ldg(&idx[n]);
    float2 t = __ldg(&tr[n]);
    float t0v = fmaxf(fmaf(t.x, g_c0[0], fmaf(t.y, g_c0[1], g_c0[2])), 0.f);
    float t1v = fmaxf(fmaf(t.x, g_c1[0], fmaf(t.y, g_c1[1], g_c1[2])), 0.f);

    __syncwarp();

    // ---------------- MMA mainloop ----------------
    const int g = lane >> 2, c = lane & 3;
    const int sw = g << 2;
    float dq[2][4], dv[2][4];
    #pragma unroll
    for (int mt = 0; mt < 2; mt++)
        #pragma unroll
        for (int i = 0; i < 4; i++) { dq[mt][i] = 0.f; dv[mt][i] = 0.f; }

    const float2* Xw = sX[warp];
    #pragma unroll
    for (int kc = 0; kc < 8; kc++) {
        int pidx = (kc * 4 + c) ^ sw;
        uint2 r0  = *(const uint2*)&Xw[(g)      * 32 + pidx];   // row g     pair
        uint2 r8  = *(const uint2*)&Xw[(g + 8)  * 32 + pidx];
        uint2 r16 = *(const uint2*)&Xw[(g + 16) * 32 + pidx];
        uint2 r24 = *(const uint2*)&Xw[(g + 24) * 32 + pidx];
        uint2 wq_ = *(const uint2*)&sWf[(g)     * 32 + pidx];   // Ntile0 = q
        uint2 wv_ = *(const uint2*)&sWf[(g + 8) * 32 + pidx];   // Ntile1 = v

        MMA_TF32(dq[0][0], dq[0][1], dq[0][2], dq[0][3], r0.x, r8.x, r0.y, r8.y, wq_.x, wq_.y);
        MMA_TF32(dv[0][0], dv[0][1], dv[0][2], dv[0][3], r0.x, r8.x, r0.y, r8.y, wv_.x, wv_.y);
        MMA_TF32(dq[1][0], dq[1][1], dq[1][2], dq[1][3], r16.x, r24.x, r16.y, r24.y, wq_.x, wq_.y);
        MMA_TF32(dv[1][0], dv[1][1], dv[1][2], dv[1][3], r16.x, r24.x, r16.y, r24.y, wv_.x, wv_.y);
    }

    // ---------------- epilogue: exp + pair-exchange + single red4 per b ----------------
    const int m0 = c << 1;
    const int mb = (c >> 1) << 2;               // quad base: 0 or 4
    float bq0 = g_bq[m0], bq1 = g_bq[m0 + 1];
    float A00 = g_A[m0][0], A01 = g_A[m0][1], A10 = g_A[m0 + 1][0], A11 = g_A[m0 + 1][1];
    float bv0 = __ldg(&bv[m0]), bv1 = __ldg(&bv[m0 + 1]);
    const bool codd = (c & 1);
    float* gf = (float*)g_buf4;
    #pragma unroll
    for (int b = 0; b < 4; b++) {
        int row = g + 8 * b;
        float t0b = __shfl_sync(0xffffffffu, t0v, row);
        float t1b = __shfl_sync(0xffffffffu, t1v, row);
        int   sgb = __shfl_sync(0xffffffffu, seg, row);
        int mt = b >> 1, hi = (b & 1) << 1;
        float q0 = dq[mt][hi]     + bq0 + t0b * A00 + t1b * A01;
        float q1 = dq[mt][hi + 1] + bq1 + t0b * A10 + t1b * A11;
        float v0 = dv[mt][hi]     + bv0;
        float v1 = dv[mt][hi + 1] + bv1;
        float e0 = __expf(q0), e1 = __expf(q1);   // |q| is O(1): no max-subtraction
        float w0 = v0 * e0,    w1 = v1 * e1;
        float ex0 = __shfl_xor_sync(0xffffffffu, e0, 1);
        float ex1 = __shfl_xor_sync(0xffffffffu, e1, 1);
        float wx0 = __shfl_xor_sync(0xffffffffu, w0, 1);
        float wx1 = __shfl_xor_sync(0xffffffffu, w1, 1);
        float a0 = codd ? wx0 : e0;
        float a1 = codd ? wx1 : e1;
        float a2 = codd ? w0  : ex0;
        float a3 = codd ? w1  : ex1;
        float* p = gf + (size_t)sgb * 16 + mb + (codd ? 8 : 0);
        red4(p, a0, a1, a2, a3);
    }
}

// ---------------- K4: out = features + tile(res/gsum, 8); re-zero g_buf4 ----------------
// Thread = (set, quarter r): fast-math divide, 2-float4 ILP chains.
__global__ void k_final(float* __restrict__ out, int nsets) {
    int tid = blockIdx.x * blockDim.x + threadIdx.x;
    int s = tid >> 3, r = tid & 7;
    bool ok = s < nsets;
    float4 gs, rs, o0, o1;
    int i0 = 0;
    if (ok) {
        int h = r & 1;
        gs = g_buf4[s * 4 + h];
        rs = g_buf4[s * 4 + 2 + h];
        i0 = s * 16 + (r >> 1) * 4 + h;
        o0 = ((float4*)out)[i0];
        o1 = ((float4*)out)[i0 + 2];
    }
    __syncwarp();
    if (ok && r < 4)
        g_buf4[s * 4 + r] = make_float4(0.f, 0.f, 0.f, 0.f);  // zero-invariant
    if (ok) {
        float wx = __fdividef(rs.x, gs.x), wy = __fdividef(rs.y, gs.y);
        float wz = __fdividef(rs.z, gs.z), ww = __fdividef(rs.w, gs.w);
        o0.x += wx; o0.y += wy; o0.z += wz; o0.w += ww;
        o1.x += wx; o1.y += wy; o1.z += wz; o1.w += ww;
        ((float4*)out)[i0]     = o0;
        ((float4*)out)[i0 + 2] = o1;
    }
}

// ---------------- launch ----------------
extern "C" void kernel_launch(void* const* d_in, const int* in_sizes, int n_in,
                              void* d_out, int out_size) {
    const float* outputs = (const float*)d_in[0];
    const float* transl  = (const float*)d_in[1];
    const int*   idx     = (const int*)  d_in[2];
    const float* Wq      = (const float*)d_in[3];
    const float* bq      = (const float*)d_in[4];
    const float* Wv      = (const float*)d_in[5];
    const float* bv      = (const float*)d_in[6];
    const float* Wp1     = (const float*)d_in[7];
    const float* gamma   = (const float*)d_in[8];
    const float* beta    = (const float*)d_in[9];
    const float* Wp2     = (const float*)d_in[10];
    const float* bp2     = (const float*)d_in[11];

    int N     = in_sizes[2];          // SIZE*NS
    int nsets = out_size / OUTP;      // SIZE

    k_stats<<<256, 256>>>((const float2*)transl, Wp1, N);
    k_prep <<<1, 256>>>(Wq, bq, Wp1, gamma, beta, Wp2, bp2, N);
    int blocks = (nsets + 3) / 4;     // 4 warps/block, 1 set/warp
    k_main <<<blocks, 128>>>((const float4*)outputs, (const float2*)transl,
                             idx, Wq, Wv, bv, (float*)d_out, nsets);
    k_final<<<(nsets * 8 + 255) / 256, 256>>>((float*)d_out, nsets);
}

// round 15
// speedup vs baseline: 1.8764x; 1.1069x over previous
#include <cuda_runtime.h>
#include <cstdint>

#define NSAMP 32
#define OUTP  64
#define MID   8
#define MAXSETS 50000

// ---------------- device scratch (zero-initialized at module load) ----------------
__device__ double g_stats[4];              // k_prep re-zeroes after reading
__device__ float  g_c0[3];                 // t0 = tr.x*c0[0] + tr.y*c0[1] + c0[2]
__device__ float  g_c1[3];
__device__ float  g_A[MID][2];             // folded relu(t) -> q coupling
__device__ float  g_bq[MID];               // b_q + Wq . b_p2
__device__ float4 g_buf4[MAXSETS * 4];     // per set: [gsum(8) | res(8)]; k_final re-zeroes

__device__ __forceinline__ void red4(float* p, float a, float b, float c, float d) {
    asm volatile("red.global.add.v4.f32 [%0], {%1,%2,%3,%4};"
                 :: "l"(p), "f"(a), "f"(b), "f"(c), "f"(d) : "memory");
}

// tf32 MMA: D[16x8] += A[16x8] @ B[8x8] (row.col). Raw f32 bits: HW truncates to tf32.
#define MMA_TF32(d0,d1,d2,d3, a0,a1,a2,a3, b0,b1) \
    asm("mma.sync.aligned.m16n8k8.row.col.f32.tf32.tf32.f32 " \
        "{%0,%1,%2,%3}, {%4,%5,%6,%7}, {%8,%9}, {%0,%1,%2,%3};" \
        : "+f"(d0), "+f"(d1), "+f"(d2), "+f"(d3) \
        : "r"(a0), "r"(a1), "r"(a2), "r"(a3), "r"(b0), "r"(b1))

// ---------------- K1: BN batch stats; block-reduced, 4 f64 atomics per BLOCK ----------
__global__ void k_stats(const float2* __restrict__ tr, const float* __restrict__ Wp1, int N) {
    __shared__ float4 sred[8];
    float w00 = __ldg(Wp1 + 0), w01 = __ldg(Wp1 + 1);
    float w10 = __ldg(Wp1 + 2), w11 = __ldg(Wp1 + 3);
    float s0 = 0.f, s1 = 0.f, q0 = 0.f, q1 = 0.f;
    for (int n = blockIdx.x * blockDim.x + threadIdx.x; n < N; n += gridDim.x * blockDim.x) {
        float2 t = __ldg(&tr[n]);
        float t0 = t.x * w00 + t.y * w01;
        float t1 = t.x * w10 + t.y * w11;
        s0 += t0; s1 += t1; q0 += t0 * t0; q1 += t1 * t1;
    }
    #pragma unroll
    for (int o = 16; o; o >>= 1) {
        s0 += __shfl_xor_sync(0xffffffffu, s0, o);
        s1 += __shfl_xor_sync(0xffffffffu, s1, o);
        q0 += __shfl_xor_sync(0xffffffffu, q0, o);
        q1 += __shfl_xor_sync(0xffffffffu, q1, o);
    }
    int warp = threadIdx.x >> 5, lane = threadIdx.x & 31;
    if (lane == 0) sred[warp] = make_float4(s0, s1, q0, q1);
    __syncthreads();
    if (warp == 0) {
        float4 v = (lane < 8) ? sred[lane] : make_float4(0.f, 0.f, 0.f, 0.f);
        #pragma unroll
        for (int o = 4; o; o >>= 1) {
            v.x += __shfl_xor_sync(0xffffffffu, v.x, o);
            v.y += __shfl_xor_sync(0xffffffffu, v.y, o);
            v.z += __shfl_xor_sync(0xffffffffu, v.z, o);
            v.w += __shfl_xor_sync(0xffffffffu, v.w, o);
        }
        if (lane == 0) {
            atomicAdd(&g_stats[0], (double)v.x);
            atomicAdd(&g_stats[1], (double)v.y);
            atomicAdd(&g_stats[2], (double)v.z);
            atomicAdd(&g_stats[3], (double)v.w);
        }
    }
}

// ---------------- K2: fold BN + p-branch; warp-per-m parallel dots -------------------
__global__ void k_prep(const float* __restrict__ Wq, const float* __restrict__ bq,
                       const float* __restrict__ Wp1, const float* __restrict__ gamma,
                       const float* __restrict__ beta, const float* __restrict__ Wp2,
                       const float* __restrict__ bp2, int N) {
    int tid = threadIdx.x;
    int m = tid >> 5, lane = tid & 31;
    float a0 = 0.f, a1 = 0.f, bb = 0.f;
    #pragma unroll
    for (int h = 0; h < 2; h++) {
        int k = lane + 32 * h;
        float w = __ldg(&Wq[m * OUTP + k]);
        a0 += w * __ldg(&Wp2[k * 2 + 0]);
        a1 += w * __ldg(&Wp2[k * 2 + 1]);
        bb += w * __ldg(&bp2[k]);
    }
    #pragma unroll
    for (int o = 16; o; o >>= 1) {
        a0 += __shfl_xor_sync(0xffffffffu, a0, o);
        a1 += __shfl_xor_sync(0xffffffffu, a1, o);
        bb += __shfl_xor_sync(0xffffffffu, bb, o);
    }
    if (lane == 0) {
        g_A[m][0] = a0; g_A[m][1] = a1; g_bq[m] = bb + __ldg(&bq[m]);
    }
    if (tid < 2) {
        double mean = g_stats[tid] / (double)N;
        double var  = g_stats[2 + tid] / (double)N - mean * mean;
        float sc = gamma[tid] / sqrtf((float)var + 1e-5f);
        float* c = tid ? g_c1 : g_c0;
        c[0] = Wp1[tid * 2 + 0] * sc;
        c[1] = Wp1[tid * 2 + 1] * sc;
        c[2] = beta[tid] - (float)mean * sc;
    }
    __syncthreads();
    if (tid < 4) g_stats[tid] = 0.0;   // restore zero-invariant for next replay
}

// ---------------- K3: persistent fused main pass (tf32 MMA, reg-prefetch pipeline) ----
// Block = 128 (4 warps), persistent. Each warp loops over sets with grid stride.
// Per iteration: STS current set (from regs) -> syncwarp -> PREFETCH next set's
// 16 float4 into registers (LDG latency overlaps MMA) -> mainloop -> epilogue.
__global__ void __launch_bounds__(128, 3) k_main(
    const float4* __restrict__ x, const float2* __restrict__ tr,
    const int* __restrict__ idx, const float* __restrict__ Wq,
    const float* __restrict__ Wv, const float* __restrict__ bv,
    float* __restrict__ out, int nsets)
{
    __shared__ float2 sWf[16 * 32];              // 4KB: [n][pair] swizzled
    __shared__ float2 sX[4][NSAMP * 32];         // 32KB: [warp][row*32 + pair] swizzled

    int tid = threadIdx.x;
    #pragma unroll
    for (int i = tid; i < 16 * 32; i += 128) {
        int nr = i >> 5, p = i & 31;
        const float* Wsrc = (nr < 8) ? (Wq + nr * OUTP) : (Wv + (nr - 8) * OUTP);
        sWf[nr * 32 + (p ^ ((nr & 7) << 2))] =
            make_float2(__ldg(&Wsrc[2 * p]), __ldg(&Wsrc[2 * p + 1]));
    }
    __syncthreads();                             // once per block lifetime

    int warp = tid >> 5, lane = tid & 31;
    const int wstride = gridDim.x * 4;
    int s_cur = blockIdx.x * 4 + warp;
    if (s_cur >= nsets) return;                  // uniform per warp

    const int half = lane >> 4;                  // sample parity this lane loads
    const int j    = lane & 15;                  // float4 group (pairs 2j, 2j+1)
    const int g = lane >> 2, c = lane & 3;
    const int sw = g << 2;
    const int m0 = c << 1;
    const int mb = (c >> 1) << 2;
    const bool codd = (c & 1);
    float bq0 = g_bq[m0], bq1 = g_bq[m0 + 1];
    float A00 = g_A[m0][0], A01 = g_A[m0][1], A10 = g_A[m0 + 1][0], A11 = g_A[m0 + 1][1];
    float bv0 = __ldg(&bv[m0]), bv1 = __ldg(&bv[m0 + 1]);
    float c00 = g_c0[0], c01 = g_c0[1], c02 = g_c0[2];
    float c10 = g_c1[0], c11 = g_c1[1], c12 = g_c1[2];
    float2* dst = sX[warp];
    const float2* Xw = sX[warp];
    float* gf = (float*)g_buf4;

    // prefetch first set
    float4 v[16];
    {
        const float4* src = x + (size_t)s_cur * NSAMP * 16;
        #pragma unroll
        for (int it = 0; it < 16; it++)
            v[it] = __ldg(&src[(it * 2 + half) * 16 + j]);
    }

    while (true) {
        // ---------------- STS staging + features (from regs) ----------------
        {
            float f0 = 0.f, f1 = 0.f, f2 = 0.f, f3 = 0.f;
            #pragma unroll
            for (int it = 0; it < 16; it++) {
                int s = it * 2 + half;
                f0 += v[it].x; f1 += v[it].y; f2 += v[it].z; f3 += v[it].w;
                int pp = (2 * j) ^ ((s & 7) << 2);   // pair-swizzle (bit0 stays 0)
                *(float4*)&dst[s * 32 + pp] = v[it];
            }
            f0 += __shfl_xor_sync(0xffffffffu, f0, 16);
            f1 += __shfl_xor_sync(0xffffffffu, f1, 16);
            f2 += __shfl_xor_sync(0xffffffffu, f2, 16);
            f3 += __shfl_xor_sync(0xffffffffu, f3, 16);
            if (lane < 16)
                ((float4*)out)[(size_t)s_cur * 16 + j] = make_float4(f0, f1, f2, f3);
        }

        // ---------------- per-sample metadata (lane = row) ----------------
        int n = s_cur * NSAMP + lane;
        int seg = __ldg(&idx[n]);
        float2 t = __ldg(&tr[n]);
        float t0v = fmaxf(fmaf(t.x, c00, fmaf(t.y, c01, c02)), 0.f);
        float t1v = fmaxf(fmaf(t.x, c10, fmaf(t.y, c11, c12)), 0.f);

        __syncwarp();

        // ---------------- PREFETCH next set (overlaps MMA below) ----------------
        int s_next = s_cur + wstride;
        bool have_next = s_next < nsets;
        if (have_next) {
            const float4* src = x + (size_t)s_next * NSAMP * 16;
            #pragma unroll
            for (int it = 0; it < 16; it++)
                v[it] = __ldg(&src[(it * 2 + half) * 16 + j]);
        }

        // ---------------- MMA mainloop ----------------
        float dq[2][4], dv[2][4];
        #pragma unroll
        for (int mt = 0; mt < 2; mt++)
            #pragma unroll
            for (int i = 0; i < 4; i++) { dq[mt][i] = 0.f; dv[mt][i] = 0.f; }

        #pragma unroll
        for (int kc = 0; kc < 8; kc++) {
            int pidx = (kc * 4 + c) ^ sw;
            uint2 r0  = *(const uint2*)&Xw[(g)      * 32 + pidx];
            uint2 r8  = *(const uint2*)&Xw[(g + 8)  * 32 + pidx];
            uint2 r16 = *(const uint2*)&Xw[(g + 16) * 32 + pidx];
            uint2 r24 = *(const uint2*)&Xw[(g + 24) * 32 + pidx];
            uint2 wq_ = *(const uint2*)&sWf[(g)     * 32 + pidx];
            uint2 wv_ = *(const uint2*)&sWf[(g + 8) * 32 + pidx];

            MMA_TF32(dq[0][0], dq[0][1], dq[0][2], dq[0][3], r0.x, r8.x, r0.y, r8.y, wq_.x, wq_.y);
            MMA_TF32(dv[0][0], dv[0][1], dv[0][2], dv[0][3], r0.x, r8.x, r0.y, r8.y, wv_.x, wv_.y);
            MMA_TF32(dq[1][0], dq[1][1], dq[1][2], dq[1][3], r16.x, r24.x, r16.y, r24.y, wq_.x, wq_.y);
            MMA_TF32(dv[1][0], dv[1][1], dv[1][2], dv[1][3], r16.x, r24.x, r16.y, r24.y, wv_.x, wv_.y);
        }

        // ---------------- epilogue: exp + pair-exchange + single red4 per b ----------
        #pragma unroll
        for (int b = 0; b < 4; b++) {
            int row = g + 8 * b;
            float t0b = __shfl_sync(0xffffffffu, t0v, row);
            float t1b = __shfl_sync(0xffffffffu, t1v, row);
            int   sgb = __shfl_sync(0xffffffffu, seg, row);
            int mt = b >> 1, hi = (b & 1) << 1;
            float q0 = dq[mt][hi]     + bq0 + t0b * A00 + t1b * A01;
            float q1 = dq[mt][hi + 1] + bq1 + t0b * A10 + t1b * A11;
            float v0 = dv[mt][hi]     + bv0;
            float v1 = dv[mt][hi + 1] + bv1;
            float e0 = __expf(q0), e1 = __expf(q1);   // |q| O(1): no max-subtraction
            float w0 = v0 * e0,    w1 = v1 * e1;
            float ex0 = __shfl_xor_sync(0xffffffffu, e0, 1);
            float ex1 = __shfl_xor_sync(0xffffffffu, e1, 1);
            float wx0 = __shfl_xor_sync(0xffffffffu, w0, 1);
            float wx1 = __shfl_xor_sync(0xffffffffu, w1, 1);
            float a0 = codd ? wx0 : e0;
            float a1 = codd ? wx1 : e1;
            float a2 = codd ? w0  : ex0;
            float a3 = codd ? w1  : ex1;
            float* p = gf + (size_t)sgb * 16 + mb + (codd ? 8 : 0);
            red4(p, a0, a1, a2, a3);
        }

        if (!have_next) break;
        s_cur = s_next;
    }
}

// ---------------- K4: out = features + tile(res/gsum, 8); re-zero g_buf4 ----------------
// Thread = (set, j in 0..3): one gs/rs load, FOUR same-parity out float4s (ILP=4).
__global__ void k_final(float* __restrict__ out, int nsets) {
    int tid = blockIdx.x * blockDim.x + threadIdx.x;
    int s = tid >> 2, j = tid & 3;
    bool ok = s < nsets;
    float4 gs, rs, o0, o1, o2, o3;
    int i0 = 0;
    if (ok) {
        int h = j & 1;
        gs = g_buf4[s * 4 + h];
        rs = g_buf4[s * 4 + 2 + h];
        i0 = s * 16 + j;                     // i = j + 4t, parity(i)=h for t=0..3
        o0 = ((float4*)out)[i0];
        o1 = ((float4*)out)[i0 + 4];
        o2 = ((float4*)out)[i0 + 8];
        o3 = ((float4*)out)[i0 + 12];
    }
    __syncwarp();
    if (ok)
        g_buf4[s * 4 + j] = make_float4(0.f, 0.f, 0.f, 0.f);  // zero-invariant
    if (ok) {
        float wx = __fdividef(rs.x, gs.x), wy = __fdividef(rs.y, gs.y);
        float wz = __fdividef(rs.z, gs.z), ww = __fdividef(rs.w, gs.w);
        o0.x += wx; o0.y += wy; o0.z += wz; o0.w += ww;
        o1.x += wx; o1.y += wy; o1.z += wz; o1.w += ww;
        o2.x += wx; o2.y += wy; o2.z += wz; o2.w += ww;
        o3.x += wx; o3.y += wy; o3.z += wz; o3.w += ww;
        ((float4*)out)[i0]      = o0;
        ((float4*)out)[i0 + 4]  = o1;
        ((float4*)out)[i0 + 8]  = o2;
        ((float4*)out)[i0 + 12] = o3;
    }
}

// ---------------- launch ----------------
extern "C" void kernel_launch(void* const* d_in, const int* in_sizes, int n_in,
                              void* d_out, int out_size) {
    const float* outputs = (const float*)d_in[0];
    const float* transl  = (const float*)d_in[1];
    const int*   idx     = (const int*)  d_in[2];
    const float* Wq      = (const float*)d_in[3];
    const float* bq      = (const float*)d_in[4];
    const float* Wv      = (const float*)d_in[5];
    const float* bv      = (const float*)d_in[6];
    const float* Wp1     = (const float*)d_in[7];
    const float* gamma   = (const float*)d_in[8];
    const float* beta    = (const float*)d_in[9];
    const float* Wp2     = (const float*)d_in[10];
    const float* bp2     = (const float*)d_in[11];

    int N     = in_sizes[2];          // SIZE*NS
    int nsets = out_size / OUTP;      // SIZE

    k_stats<<<256, 256>>>((const float2*)transl, Wp1, N);
    k_prep <<<1, 256>>>(Wq, bq, Wp1, gamma, beta, Wp2, bp2, N);
    int blocks = 148 * 3;             // persistent: 3 blocks/SM target
    if (blocks * 4 > nsets) blocks = (nsets + 3) / 4;
    k_main <<<blocks, 128>>>((const float4*)outputs, (const float2*)transl,
                             idx, Wq, Wv, bv, (float*)d_out, nsets);
    k_final<<<(nsets * 4 + 255) / 256, 256>>>((float*)d_out, nsets);
}

// round 16
// speedup vs baseline: 1.9237x; 1.0252x over previous
#include <cuda_runtime.h>
#include <cstdint>

#define NSAMP 32
#define OUTP  64
#define MID   8
#define MAXSETS 50000

// ---------------- device scratch (zero-initialized at module load) ----------------
__device__ double g_stats[4];              // k_prep re-zeroes after reading
__device__ float  g_c0[3];                 // t0 = tr.x*c0[0] + tr.y*c0[1] + c0[2]
__device__ float  g_c1[3];
__device__ float  g_A[MID][2];             // folded relu(t) -> q coupling
__device__ float  g_bq[MID];               // b_q + Wq . b_p2
__device__ float4 g_buf4[MAXSETS * 4];     // per set: [gsum(8) | res(8)]; k_final re-zeroes

__device__ __forceinline__ void red4(float* p, float a, float b, float c, float d) {
    asm volatile("red.global.add.v4.f32 [%0], {%1,%2,%3,%4};"
                 :: "l"(p), "f"(a), "f"(b), "f"(c), "f"(d) : "memory");
}

// tf32 MMA: D[16x8] += A[16x8] @ B[8x8] (row.col). Raw f32 bits: HW truncates to tf32.
#define MMA_TF32(d0,d1,d2,d3, a0,a1,a2,a3, b0,b1) \
    asm("mma.sync.aligned.m16n8k8.row.col.f32.tf32.tf32.f32 " \
        "{%0,%1,%2,%3}, {%4,%5,%6,%7}, {%8,%9}, {%0,%1,%2,%3};" \
        : "+f"(d0), "+f"(d1), "+f"(d2), "+f"(d3) \
        : "r"(a0), "r"(a1), "r"(a2), "r"(a3), "r"(b0), "r"(b1))

// ---------------- K1: BN batch stats; block-reduced, 4 f64 atomics per BLOCK ----------
__global__ void k_stats(const float2* __restrict__ tr, const float* __restrict__ Wp1, int N) {
    __shared__ float4 sred[8];
    float w00 = __ldg(Wp1 + 0), w01 = __ldg(Wp1 + 1);
    float w10 = __ldg(Wp1 + 2), w11 = __ldg(Wp1 + 3);
    float s0 = 0.f, s1 = 0.f, q0 = 0.f, q1 = 0.f;
    for (int n = blockIdx.x * blockDim.x + threadIdx.x; n < N; n += gridDim.x * blockDim.x) {
        float2 t = __ldg(&tr[n]);
        float t0 = t.x * w00 + t.y * w01;
        float t1 = t.x * w10 + t.y * w11;
        s0 += t0; s1 += t1; q0 += t0 * t0; q1 += t1 * t1;
    }
    #pragma unroll
    for (int o = 16; o; o >>= 1) {
        s0 += __shfl_xor_sync(0xffffffffu, s0, o);
        s1 += __shfl_xor_sync(0xffffffffu, s1, o);
        q0 += __shfl_xor_sync(0xffffffffu, q0, o);
        q1 += __shfl_xor_sync(0xffffffffu, q1, o);
    }
    int warp = threadIdx.x >> 5, lane = threadIdx.x & 31;
    if (lane == 0) sred[warp] = make_float4(s0, s1, q0, q1);
    __syncthreads();
    if (warp == 0) {
        float4 v = (lane < 8) ? sred[lane] : make_float4(0.f, 0.f, 0.f, 0.f);
        #pragma unroll
        for (int o = 4; o; o >>= 1) {
            v.x += __shfl_xor_sync(0xffffffffu, v.x, o);
            v.y += __shfl_xor_sync(0xffffffffu, v.y, o);
            v.z += __shfl_xor_sync(0xffffffffu, v.z, o);
            v.w += __shfl_xor_sync(0xffffffffu, v.w, o);
        }
        if (lane == 0) {
            atomicAdd(&g_stats[0], (double)v.x);
            atomicAdd(&g_stats[1], (double)v.y);
            atomicAdd(&g_stats[2], (double)v.z);
            atomicAdd(&g_stats[3], (double)v.w);
        }
    }
}

// ---------------- K2: fold BN + p-branch; warp-per-m parallel dots -------------------
__global__ void k_prep(const float* __restrict__ Wq, const float* __restrict__ bq,
                       const float* __restrict__ Wp1, const float* __restrict__ gamma,
                       const float* __restrict__ beta, const float* __restrict__ Wp2,
                       const float* __restrict__ bp2, int N) {
    int tid = threadIdx.x;
    int m = tid >> 5, lane = tid & 31;
    float a0 = 0.f, a1 = 0.f, bb = 0.f;
    #pragma unroll
    for (int h = 0; h < 2; h++) {
        int k = lane + 32 * h;
        float w = __ldg(&Wq[m * OUTP + k]);
        a0 += w * __ldg(&Wp2[k * 2 + 0]);
        a1 += w * __ldg(&Wp2[k * 2 + 1]);
        bb += w * __ldg(&bp2[k]);
    }
    #pragma unroll
    for (int o = 16; o; o >>= 1) {
        a0 += __shfl_xor_sync(0xffffffffu, a0, o);
        a1 += __shfl_xor_sync(0xffffffffu, a1, o);
        bb += __shfl_xor_sync(0xffffffffu, bb, o);
    }
    if (lane == 0) {
        g_A[m][0] = a0; g_A[m][1] = a1; g_bq[m] = bb + __ldg(&bq[m]);
    }
    if (tid < 2) {
        double mean = g_stats[tid] / (double)N;
        double var  = g_stats[2 + tid] / (double)N - mean * mean;
        float sc = gamma[tid] / sqrtf((float)var + 1e-5f);
        float* c = tid ? g_c1 : g_c0;
        c[0] = Wp1[tid * 2 + 0] * sc;
        c[1] = Wp1[tid * 2 + 1] * sc;
        c[2] = beta[tid] - (float)mean * sc;
    }
    __syncthreads();
    if (tid < 4) g_stats[tid] = 0.0;   // restore zero-invariant for next replay
}

// ---------------- K3: persistent fused main pass (tf32 MMA, reg-prefetch pipeline) ----
// Block = 128 (4 warps), persistent, 4 blocks/SM (128-reg cap: trades a few
// rematerialized loads for +33% latency-hiding warps; the loop is latency-bound
// at ~13% issue so the extra instructions are free).
__global__ void __launch_bounds__(128, 4) k_main(
    const float4* __restrict__ x, const float2* __restrict__ tr,
    const int* __restrict__ idx, const float* __restrict__ Wq,
    const float* __restrict__ Wv, const float* __restrict__ bv,
    float* __restrict__ out, int nsets)
{
    __shared__ float2 sWf[16 * 32];              // 4KB: [n][pair] swizzled
    __shared__ float2 sX[4][NSAMP * 32];         // 32KB: [warp][row*32 + pair] swizzled

    int tid = threadIdx.x;
    #pragma unroll
    for (int i = tid; i < 16 * 32; i += 128) {
        int nr = i >> 5, p = i & 31;
        const float* Wsrc = (nr < 8) ? (Wq + nr * OUTP) : (Wv + (nr - 8) * OUTP);
        sWf[nr * 32 + (p ^ ((nr & 7) << 2))] =
            make_float2(__ldg(&Wsrc[2 * p]), __ldg(&Wsrc[2 * p + 1]));
    }
    __syncthreads();                             // once per block lifetime

    int warp = tid >> 5, lane = tid & 31;
    const int wstride = gridDim.x * 4;
    int s_cur = blockIdx.x * 4 + warp;
    if (s_cur >= nsets) return;                  // uniform per warp

    const int half = lane >> 4;                  // sample parity this lane loads
    const int j    = lane & 15;                  // float4 group (pairs 2j, 2j+1)
    const int g = lane >> 2, c = lane & 3;
    const int sw = g << 2;
    const int m0 = c << 1;
    const int mb = (c >> 1) << 2;
    const bool codd = (c & 1);
    float bq0 = g_bq[m0], bq1 = g_bq[m0 + 1];
    float A00 = g_A[m0][0], A01 = g_A[m0][1], A10 = g_A[m0 + 1][0], A11 = g_A[m0 + 1][1];
    float bv0 = __ldg(&bv[m0]), bv1 = __ldg(&bv[m0 + 1]);
    float c00 = g_c0[0], c01 = g_c0[1], c02 = g_c0[2];
    float c10 = g_c1[0], c11 = g_c1[1], c12 = g_c1[2];
    float2* dst = sX[warp];
    const float2* Xw = sX[warp];
    float* gf = (float*)g_buf4;

    // prefetch first set
    float4 v[16];
    {
        const float4* src = x + (size_t)s_cur * NSAMP * 16;
        #pragma unroll
        for (int it = 0; it < 16; it++)
            v[it] = __ldg(&src[(it * 2 + half) * 16 + j]);
    }

    while (true) {
        // ---------------- STS staging + features (from regs) ----------------
        {
            float f0 = 0.f, f1 = 0.f, f2 = 0.f, f3 = 0.f;
            #pragma unroll
            for (int it = 0; it < 16; it++) {
                int s = it * 2 + half;
                f0 += v[it].x; f1 += v[it].y; f2 += v[it].z; f3 += v[it].w;
                int pp = (2 * j) ^ ((s & 7) << 2);   // pair-swizzle (bit0 stays 0)
                *(float4*)&dst[s * 32 + pp] = v[it];
            }
            f0 += __shfl_xor_sync(0xffffffffu, f0, 16);
            f1 += __shfl_xor_sync(0xffffffffu, f1, 16);
            f2 += __shfl_xor_sync(0xffffffffu, f2, 16);
            f3 += __shfl_xor_sync(0xffffffffu, f3, 16);
            if (lane < 16)
                ((float4*)out)[(size_t)s_cur * 16 + j] = make_float4(f0, f1, f2, f3);
        }

        // ---------------- per-sample metadata (lane = row) ----------------
        int n = s_cur * NSAMP + lane;
        int seg = __ldg(&idx[n]);
        float2 t = __ldg(&tr[n]);
        float t0v = fmaxf(fmaf(t.x, c00, fmaf(t.y, c01, c02)), 0.f);
        float t1v = fmaxf(fmaf(t.x, c10, fmaf(t.y, c11, c12)), 0.f);

        __syncwarp();

        // ---------------- PREFETCH next set (overlaps MMA below) ----------------
        int s_next = s_cur + wstride;
        bool have_next = s_next < nsets;
        if (have_next) {
            const float4* src = x + (size_t)s_next * NSAMP * 16;
            #pragma unroll
            for (int it = 0; it < 16; it++)
                v[it] = __ldg(&src[(it * 2 + half) * 16 + j]);
        }

        // ---------------- MMA mainloop ----------------
        float dq[2][4], dv[2][4];
        #pragma unroll
        for (int mt = 0; mt < 2; mt++)
            #pragma unroll
            for (int i = 0; i < 4; i++) { dq[mt][i] = 0.f; dv[mt][i] = 0.f; }

        #pragma unroll
        for (int kc = 0; kc < 8; kc++) {
            int pidx = (kc * 4 + c) ^ sw;
            uint2 r0  = *(const uint2*)&Xw[(g)      * 32 + pidx];
            uint2 r8  = *(const uint2*)&Xw[(g + 8)  * 32 + pidx];
            uint2 r16 = *(const uint2*)&Xw[(g + 16) * 32 + pidx];
            uint2 r24 = *(const uint2*)&Xw[(g + 24) * 32 + pidx];
            uint2 wq_ = *(const uint2*)&sWf[(g)     * 32 + pidx];
            uint2 wv_ = *(const uint2*)&sWf[(g + 8) * 32 + pidx];

            MMA_TF32(dq[0][0], dq[0][1], dq[0][2], dq[0][3], r0.x, r8.x, r0.y, r8.y, wq_.x, wq_.y);
            MMA_TF32(dv[0][0], dv[0][1], dv[0][2], dv[0][3], r0.x, r8.x, r0.y, r8.y, wv_.x, wv_.y);
            MMA_TF32(dq[1][0], dq[1][1], dq[1][2], dq[1][3], r16.x, r24.x, r16.y, r24.y, wq_.x, wq_.y);
            MMA_TF32(dv[1][0], dv[1][1], dv[1][2], dv[1][3], r16.x, r24.x, r16.y, r24.y, wv_.x, wv_.y);
        }

        // ---------------- epilogue: exp + pair-exchange + single red4 per b ----------
        #pragma unroll
        for (int b = 0; b < 4; b++) {
            int row = g + 8 * b;
            float t0b = __shfl_sync(0xffffffffu, t0v, row);
            float t1b = __shfl_sync(0xffffffffu, t1v, row);
            int   sgb = __shfl_sync(0xffffffffu, seg, row);
            int mt = b >> 1, hi = (b & 1) << 1;
            float q0 = dq[mt][hi]     + bq0 + t0b * A00 + t1b * A01;
            float q1 = dq[mt][hi + 1] + bq1 + t0b * A10 + t1b * A11;
            float v0 = dv[mt][hi]     + bv0;
            float v1 = dv[mt][hi + 1] + bv1;
            float e0 = __expf(q0), e1 = __expf(q1);   // |q| O(1): no max-subtraction
            float w0 = v0 * e0,    w1 = v1 * e1;
            float ex0 = __shfl_xor_sync(0xffffffffu, e0, 1);
            float ex1 = __shfl_xor_sync(0xffffffffu, e1, 1);
            float wx0 = __shfl_xor_sync(0xffffffffu, w0, 1);
            float wx1 = __shfl_xor_sync(0xffffffffu, w1, 1);
            float a0 = codd ? wx0 : e0;
            float a1 = codd ? wx1 : e1;
            float a2 = codd ? w0  : ex0;
            float a3 = codd ? w1  : ex1;
            float* p = gf + (size_t)sgb * 16 + mb + (codd ? 8 : 0);
            red4(p, a0, a1, a2, a3);
        }

        if (!have_next) break;
        s_cur = s_next;
    }
}

// ---------------- K4: out = features + tile(res/gsum, 8); re-zero g_buf4 ----------------
// Thread = (set, j in 0..3): one gs/rs load, FOUR same-parity out float4s (ILP=4).
__global__ void k_final(float* __restrict__ out, int nsets) {
    int tid = blockIdx.x * blockDim.x + threadIdx.x;
    int s = tid >> 2, j = tid & 3;
    bool ok = s < nsets;
    float4 gs, rs, o0, o1, o2, o3;
    int i0 = 0;
    if (ok) {
        int h = j & 1;
        gs = g_buf4[s * 4 + h];
        rs = g_buf4[s * 4 + 2 + h];
        i0 = s * 16 + j;                     // i = j + 4t, parity(i)=h for t=0..3
        o0 = ((float4*)out)[i0];
        o1 = ((float4*)out)[i0 + 4];
        o2 = ((float4*)out)[i0 + 8];
        o3 = ((float4*)out)[i0 + 12];
    }
    __syncwarp();
    if (ok)
        g_buf4[s * 4 + j] = make_float4(0.f, 0.f, 0.f, 0.f);  // zero-invariant
    if (ok) {
        float wx = __fdividef(rs.x, gs.x), wy = __fdividef(rs.y, gs.y);
        float wz = __fdividef(rs.z, gs.z), ww = __fdividef(rs.w, gs.w);
        o0.x += wx; o0.y += wy; o0.z += wz; o0.w += ww;
        o1.x += wx; o1.y += wy; o1.z += wz; o1.w += ww;
        o2.x += wx; o2.y += wy; o2.z += wz; o2.w += ww;
        o3.x += wx; o3.y += wy; o3.z += wz; o3.w += ww;
        ((float4*)out)[i0]      = o0;
        ((float4*)out)[i0 + 4]  = o1;
        ((float4*)out)[i0 + 8]  = o2;
        ((float4*)out)[i0 + 12] = o3;
    }
}

// ---------------- launch ----------------
extern "C" void kernel_launch(void* const* d_in, const int* in_sizes, int n_in,
                              void* d_out, int out_size) {
    const float* outputs = (const float*)d_in[0];
    const float* transl  = (const float*)d_in[1];
    const int*   idx     = (const int*)  d_in[2];
    const float* Wq      = (const float*)d_in[3];
    const float* bq      = (const float*)d_in[4];
    const float* Wv      = (const float*)d_in[5];
    const float* bv      = (const float*)d_in[6];
    const float* Wp1     = (const float*)d_in[7];
    const float* gamma   = (const float*)d_in[8];
    const float* beta    = (const float*)d_in[9];
    const float* Wp2     = (const float*)d_in[10];
    const float* bp2     = (const float*)d_in[11];

    int N     = in_sizes[2];          // SIZE*NS
    int nsets = out_size / OUTP;      // SIZE

    k_stats<<<256, 256>>>((const float2*)transl, Wp1, N);
    k_prep <<<1, 256>>>(Wq, bq, Wp1, gamma, beta, Wp2, bp2, N);
    int blocks = 148 * 4;             // persistent: 4 blocks/SM target
    if (blocks * 4 > nsets) blocks = (nsets + 3) / 4;
    k_main <<<blocks, 128>>>((const float4*)outputs, (const float2*)transl,
                             idx, Wq, Wv, bv, (float*)d_out, nsets);
    k_final<<<(nsets * 4 + 255) / 256, 256>>>((float*)d_out, nsets);
}